// round 1
// baseline (speedup 1.0000x reference)
#include <cuda_runtime.h>
#include <math.h>

// ---------------------------------------------------------------------------
// Problem constants (fixed by the reference setup)
// ---------------------------------------------------------------------------
#define L_TOT   4096
#define HID     2560
#define NH      8
#define NKV     4
#define HD      256
#define QD      (NH*HD)    // 2048
#define KD      (NKV*HD)   // 1024
#define SEQ     1024       // each packed sequence length
#define NSEQ    4
#define SCALING 0.0625f    // 256^-0.5
#define EPS     1e-6f

// ---------------------------------------------------------------------------
// Scratch (static device globals; no allocation allowed)
// ---------------------------------------------------------------------------
__device__ float g_q[(size_t)L_TOT * QD];            // 32 MB
__device__ float g_k[(size_t)L_TOT * KD];            // 16 MB
__device__ float g_v[(size_t)L_TOT * KD];            // 16 MB
__device__ float g_attn[(size_t)L_TOT * QD];         // 32 MB
__device__ float g_scores[(size_t)NH * L_TOT * SEQ]; // 128 MB

// ---------------------------------------------------------------------------
// Register-blocked SGEMM: 128x128 tile, BK=16, 256 threads, 8x8 per thread.
// TRANSB=false: C = A(MxK, lda) * B(KxN, ldb)
// TRANSB=true : C = A(MxK, lda) * B(NxK, ldb)^T
// EPI=0: plain store. EPI=1: scale by SCALING + causal mask (col>row -> -inf),
//        with fully-masked-tile early-out.
// All dims must divide the tile sizes (they do for this problem).
// ---------------------------------------------------------------------------
#define BM 128
#define BN 128
#define BK 16

template<bool TRANSB, int EPI>
__device__ __forceinline__ void gemm_tile(
    const float* __restrict__ A, const float* __restrict__ B, float* __restrict__ C,
    int K, int lda, int ldb, int ldc)
{
    __shared__ float As[BK][BM + 4];
    __shared__ float Bs[BK][BN + 4];

    const int m0 = blockIdx.y * BM;
    const int n0 = blockIdx.x * BN;
    const int t  = threadIdx.x;

    if (EPI == 1 && n0 > m0 + (BM - 1)) {
        // entire tile above the causal diagonal: write -inf, skip the math
        const float4 ninf = make_float4(-INFINITY, -INFINITY, -INFINITY, -INFINITY);
        for (int i = t; i < BM * (BN / 4); i += 256) {
            int r = i >> 5;        // / (BN/4)
            int c = i & 31;        // % (BN/4)
            *(float4*)(C + (size_t)(m0 + r) * ldc + n0 + c * 4) = ninf;
        }
        return;
    }

    const int tx = t & 15;
    const int ty = t >> 4;

    float acc[8][8];
#pragma unroll
    for (int i = 0; i < 8; i++)
#pragma unroll
        for (int j = 0; j < 8; j++) acc[i][j] = 0.f;

    for (int k0 = 0; k0 < K; k0 += BK) {
        // ---- load A tile (BMxBK), transposed into As[k][m]
#pragma unroll
        for (int l = 0; l < 2; l++) {
            int idx = t + l * 256;
            int r = idx >> 2, c4 = idx & 3;
            float4 va = *(const float4*)(A + (size_t)(m0 + r) * lda + k0 + c4 * 4);
            As[c4 * 4 + 0][r] = va.x;
            As[c4 * 4 + 1][r] = va.y;
            As[c4 * 4 + 2][r] = va.z;
            As[c4 * 4 + 3][r] = va.w;
        }
        // ---- load B tile into Bs[k][n]
        if (TRANSB) {
            int c = t & 15, r0 = t >> 4;
#pragma unroll
            for (int l = 0; l < 8; l++) {
                int r = r0 + l * 16;
                Bs[c][r] = B[(size_t)(n0 + r) * ldb + k0 + c];
            }
        } else {
#pragma unroll
            for (int l = 0; l < 2; l++) {
                int idx = t + l * 256;
                int r = idx >> 5, c4 = idx & 31;
                *(float4*)&Bs[r][c4 * 4] =
                    *(const float4*)(B + (size_t)(k0 + r) * ldb + n0 + c4 * 4);
            }
        }
        __syncthreads();

#pragma unroll
        for (int k = 0; k < BK; k++) {
            float a[8], b[8];
            *(float4*)&a[0] = *(const float4*)&As[k][ty * 8];
            *(float4*)&a[4] = *(const float4*)&As[k][ty * 8 + 4];
            *(float4*)&b[0] = *(const float4*)&Bs[k][tx * 8];
            *(float4*)&b[4] = *(const float4*)&Bs[k][tx * 8 + 4];
#pragma unroll
            for (int i = 0; i < 8; i++)
#pragma unroll
                for (int j = 0; j < 8; j++)
                    acc[i][j] += a[i] * b[j];
        }
        __syncthreads();
    }

#pragma unroll
    for (int i = 0; i < 8; i++) {
        int m = m0 + ty * 8 + i;
#pragma unroll
        for (int jj = 0; jj < 2; jj++) {
            int n = n0 + tx * 8 + jj * 4;
            float4 v4;
            if (EPI == 1) {
                float vv[4];
#pragma unroll
                for (int q = 0; q < 4; q++) {
                    float x = acc[i][jj * 4 + q] * SCALING;
                    vv[q] = (n + q > m) ? -INFINITY : x;
                }
                v4 = make_float4(vv[0], vv[1], vv[2], vv[3]);
            } else {
                v4 = make_float4(acc[i][jj * 4 + 0], acc[i][jj * 4 + 1],
                                 acc[i][jj * 4 + 2], acc[i][jj * 4 + 3]);
            }
            *(float4*)(C + (size_t)m * ldc + n) = v4;
        }
    }
}

// ---------------------------------------------------------------------------
// GEMM wrappers
// ---------------------------------------------------------------------------
__global__ __launch_bounds__(256) void k_proj_q(const float* __restrict__ hs,
                                                const float* __restrict__ W)
{ gemm_tile<false, 0>(hs, W, g_q, HID, HID, QD, QD); }

__global__ __launch_bounds__(256) void k_proj_k(const float* __restrict__ hs,
                                                const float* __restrict__ W)
{ gemm_tile<false, 0>(hs, W, g_k, HID, HID, KD, KD); }

__global__ __launch_bounds__(256) void k_proj_v(const float* __restrict__ hs,
                                                const float* __restrict__ W)
{ gemm_tile<false, 0>(hs, W, g_v, HID, HID, KD, KD); }

// S[h,s] = scale * Q_hs (SEQ x HD) * K_hs^T  with causal mask
__global__ __launch_bounds__(256) void k_scores()
{
    int z = blockIdx.z;
    int h = z >> 2, s = z & 3;
    const float* A = g_q + (size_t)s * SEQ * QD + h * HD;
    const float* B = g_k + (size_t)s * SEQ * KD + (h >> 1) * HD;
    float* C = g_scores + ((size_t)h * L_TOT + (size_t)s * SEQ) * SEQ;
    gemm_tile<true, 1>(A, B, C, HD, QD, KD, SEQ);
}

// O[h,s] = P (SEQ x SEQ) * V_hs (SEQ x HD)
__global__ __launch_bounds__(256) void k_pv()
{
    int z = blockIdx.z;
    int h = z >> 2, s = z & 3;
    const float* A = g_scores + ((size_t)h * L_TOT + (size_t)s * SEQ) * SEQ;
    const float* B = g_v + (size_t)s * SEQ * KD + (h >> 1) * HD;
    float* C = g_attn + (size_t)s * SEQ * QD + h * HD;
    gemm_tile<false, 0>(A, B, C, SEQ, SEQ, KD, QD);
}

__global__ __launch_bounds__(256) void k_out(const float* __restrict__ Wo,
                                             float* __restrict__ out)
{ gemm_tile<false, 0>(g_attn, Wo, out, QD, QD, HID, HID); }

// ---------------------------------------------------------------------------
// RMSNorm (over HD) + RoPE, in place. grid = (token, head), 256 threads.
// ---------------------------------------------------------------------------
__device__ __forceinline__ void rmsrope_body(float* __restrict__ x,
                                             const float* __restrict__ w,
                                             const float* __restrict__ cosp,
                                             const float* __restrict__ sinp,
                                             int nh)
{
    int tok = blockIdx.x;
    int h   = blockIdx.y;
    float* p = x + ((size_t)tok * nh + h) * HD;
    int d = threadIdx.x;

    float v = p[d];
    float ssq = v * v;
#pragma unroll
    for (int o = 16; o > 0; o >>= 1) ssq += __shfl_xor_sync(0xffffffffu, ssq, o);
    __shared__ float ws[8];
    if ((d & 31) == 0) ws[d >> 5] = ssq;
    __syncthreads();
    float tot = 0.f;
#pragma unroll
    for (int i = 0; i < 8; i++) tot += ws[i];
    float r = rsqrtf(tot * (1.0f / HD) + EPS);
    float nv = v * r * (1.0f + w[d]);

    __shared__ float sn[HD];
    sn[d] = nv;
    __syncthreads();
    float rot = (d < HD / 2) ? -sn[d + HD / 2] : sn[d - HD / 2];
    p[d] = nv * cosp[(size_t)tok * HD + d] + rot * sinp[(size_t)tok * HD + d];
}

__global__ __launch_bounds__(256) void k_rope_q(const float* w, const float* c, const float* s)
{ rmsrope_body(g_q, w, c, s, NH); }

__global__ __launch_bounds__(256) void k_rope_k(const float* w, const float* c, const float* s)
{ rmsrope_body(g_k, w, c, s, NKV); }

// ---------------------------------------------------------------------------
// Row softmax over 1024 entries. One block (256 threads, float4 each) per row.
// Masked entries are exactly -inf -> exp gives 0.
// ---------------------------------------------------------------------------
__global__ __launch_bounds__(256) void k_softmax()
{
    float* row = g_scores + (size_t)blockIdx.x * SEQ;
    int d = threadIdx.x;
    float4 v = *(float4*)(row + d * 4);

    float m = fmaxf(fmaxf(v.x, v.y), fmaxf(v.z, v.w));
#pragma unroll
    for (int o = 16; o > 0; o >>= 1) m = fmaxf(m, __shfl_xor_sync(0xffffffffu, m, o));
    __shared__ float wm[8];
    if ((d & 31) == 0) wm[d >> 5] = m;
    __syncthreads();
    float gm = wm[0];
#pragma unroll
    for (int i = 1; i < 8; i++) gm = fmaxf(gm, wm[i]);

    v.x = __expf(v.x - gm);
    v.y = __expf(v.y - gm);
    v.z = __expf(v.z - gm);
    v.w = __expf(v.w - gm);

    float ssum = v.x + v.y + v.z + v.w;
#pragma unroll
    for (int o = 16; o > 0; o >>= 1) ssum += __shfl_xor_sync(0xffffffffu, ssum, o);
    __shared__ float wsum[8];
    if ((d & 31) == 0) wsum[d >> 5] = ssum;
    __syncthreads();
    float tot = 0.f;
#pragma unroll
    for (int i = 0; i < 8; i++) tot += wsum[i];
    float inv = 1.0f / tot;

    v.x *= inv; v.y *= inv; v.z *= inv; v.w *= inv;
    *(float4*)(row + d * 4) = v;
}

// ---------------------------------------------------------------------------
// kernel_launch
// Input order: hidden_states, cos, sin, Wq, Wk, Wv, Wo, q_norm_w, k_norm_w, cu_seqlens
// ---------------------------------------------------------------------------
extern "C" void kernel_launch(void* const* d_in, const int* in_sizes, int n_in,
                              void* d_out, int out_size)
{
    const float* hs   = (const float*)d_in[0];
    const float* cosp = (const float*)d_in[1];
    const float* sinp = (const float*)d_in[2];
    const float* Wq   = (const float*)d_in[3];
    const float* Wk   = (const float*)d_in[4];
    const float* Wv   = (const float*)d_in[5];
    const float* Wo   = (const float*)d_in[6];
    const float* qw   = (const float*)d_in[7];
    const float* kw   = (const float*)d_in[8];
    float* out = (float*)d_out;

    dim3 thr(256);

    k_proj_q<<<dim3(QD / BN, L_TOT / BM), thr>>>(hs, Wq);
    k_proj_k<<<dim3(KD / BN, L_TOT / BM), thr>>>(hs, Wk);
    k_proj_v<<<dim3(KD / BN, L_TOT / BM), thr>>>(hs, Wv);

    k_rope_q<<<dim3(L_TOT, NH), thr>>>(qw, cosp, sinp);
    k_rope_k<<<dim3(L_TOT, NKV), thr>>>(kw, cosp, sinp);

    k_scores<<<dim3(SEQ / BN, SEQ / BM, NH * NSEQ), thr>>>();
    k_softmax<<<NH * L_TOT, thr>>>();
    k_pv<<<dim3(HD / BN, SEQ / BM, NH * NSEQ), thr>>>();

    k_out<<<dim3(HID / BN, L_TOT / BM), thr>>>(Wo, out);
}

// round 5
// speedup vs baseline: 2.3907x; 2.3907x over previous
#include <cuda_runtime.h>
#include <math.h>
#include <stdint.h>

// ---------------------------------------------------------------------------
// Problem constants
// ---------------------------------------------------------------------------
#define L_TOT   4096
#define HID     2560
#define NH      8
#define NKV     4
#define HD      256
#define QD      (NH*HD)    // 2048
#define KD      (NKV*HD)   // 1024
#define SEQ     1024
#define NSEQ    4
#define SCALING 0.0625f
#define EPS     1e-6f

// ---------------------------------------------------------------------------
// Scratch (__device__ globals; no allocation allowed)
// ---------------------------------------------------------------------------
__device__ float g_hs [(size_t)L_TOT * HID];
__device__ float g_WqT[(size_t)QD * HID];
__device__ float g_WkT[(size_t)KD * HID];
__device__ float g_WvT[(size_t)KD * HID];
__device__ float g_WoT[(size_t)HID * QD];
__device__ float g_q  [(size_t)L_TOT * QD];
__device__ float g_k  [(size_t)L_TOT * KD];
__device__ float g_v  [(size_t)L_TOT * KD];
__device__ float g_vt [(size_t)NSEQ * NKV * HD * SEQ]; // per (s,kv): [d][t]
__device__ float g_attn[(size_t)L_TOT * QD];
__device__ float g_scores[(size_t)NH * L_TOT * SEQ];

// ---------------------------------------------------------------------------
// Helpers
// ---------------------------------------------------------------------------
__device__ __forceinline__ uint32_t smem_u32(const void* p) {
    uint32_t a;
    asm("{ .reg .u64 t; cvta.to.shared.u64 t, %1; cvt.u32.u64 %0, t; }"
        : "=r"(a) : "l"(p));
    return a;
}
// tf32 round-to-nearest (b32 destination register)
__device__ __forceinline__ float rna_tf32(float x) {
    uint32_t o;
    asm("cvt.rna.tf32.f32 %0, %1;" : "=r"(o) : "f"(x));
    return __uint_as_float(o);
}
__device__ __forceinline__ void cp_async16(uint32_t dst, const void* src) {
    asm volatile("cp.async.ca.shared.global [%0], [%1], 16;" :: "r"(dst), "l"(src));
}
#define CP_COMMIT()  asm volatile("cp.async.commit_group;" ::: "memory")
#define CP_WAIT(n)   asm volatile("cp.async.wait_group %0;" :: "n"(n) : "memory")

// mma.sync m16n8k8 tf32: d = a*b + d
__device__ __forceinline__ void mma_tf32(float* c, const uint32_t* a, const uint32_t* b) {
    asm volatile(
        "mma.sync.aligned.m16n8k8.row.col.f32.tf32.tf32.f32 "
        "{%0,%1,%2,%3}, {%4,%5,%6,%7}, {%8,%9}, {%0,%1,%2,%3};"
        : "+f"(c[0]), "+f"(c[1]), "+f"(c[2]), "+f"(c[3])
        : "r"(a[0]), "r"(a[1]), "r"(a[2]), "r"(a[3]), "r"(b[0]), "r"(b[1]));
}

// ---------------------------------------------------------------------------
// tf32 mma.sync GEMM: C(MxN) = A(MxK) * B(NxK)^T
// CTA 128x128, BK=16, 256 thr (8 warps, 2x4), warp tile 64x32, cp.async x2 buf
// mode: 0=plain, 1=scores batch, 2=pv batch.  epi: 0=none, 1=scale+mask, 2=rna
// ---------------------------------------------------------------------------
#define BM 128
#define BN 128
#define BK 16
#define BKP 20   // padded stride (floats): conflict-free fragment LDS

__global__ __launch_bounds__(256) void k_gemm(
    const float* __restrict__ A, const float* __restrict__ B, float* __restrict__ C,
    int lda, int ldb, int ldc, int K, int mode, int epi)
{
    const int t    = threadIdx.x;
    const int lane = t & 31;
    const int wid  = t >> 5;
    const int grp  = lane >> 2;   // 0..7
    const int qid  = lane & 3;    // 0..3
    const int wm   = (wid >> 2) * 64;  // warp M offset (0/64)
    const int wn   = (wid & 3) * 32;   // warp N offset (0/32/64/96)
    const int m0   = blockIdx.y * BM;
    const int n0   = blockIdx.x * BN;

    if (mode == 1) {
        int h = blockIdx.z >> 2, s = blockIdx.z & 3;
        A = g_q + (size_t)s * SEQ * QD + h * HD;                    lda = QD;
        B = g_k + (size_t)s * SEQ * KD + (h >> 1) * HD;             ldb = KD;
        C = g_scores + ((size_t)h * L_TOT + (size_t)s * SEQ) * SEQ; ldc = SEQ;
    } else if (mode == 2) {
        int h = blockIdx.z >> 2, s = blockIdx.z & 3;
        A = g_scores + ((size_t)h * L_TOT + (size_t)s * SEQ) * SEQ; lda = SEQ;
        B = g_vt + ((size_t)(s * NKV + (h >> 1))) * HD * SEQ;       ldb = SEQ;
        C = g_attn + (size_t)s * SEQ * QD + h * HD;                 ldc = QD;
    }

    // fully above the causal diagonal: fill -inf, skip the math
    if (epi == 1 && n0 > m0 + (BM - 1)) {
        const float4 ninf = make_float4(-INFINITY, -INFINITY, -INFINITY, -INFINITY);
#pragma unroll
        for (int l = 0; l < 16; ++l) {
            int idx = t + (l << 8);
            int r = idx >> 5, c4 = idx & 31;
            *(float4*)(C + (size_t)(m0 + r) * ldc + n0 + (c4 << 2)) = ninf;
        }
        return;
    }

    __shared__ float As[2][BM][BKP];
    __shared__ float Bs[2][BN][BKP];

    float acc[4][4][4];
#pragma unroll
    for (int mi = 0; mi < 4; ++mi)
#pragma unroll
        for (int ni = 0; ni < 4; ++ni)
#pragma unroll
            for (int q = 0; q < 4; ++q) acc[mi][ni][q] = 0.f;

    const int nc = K >> 4;   // chunks of 16

    // per-thread staging coords: idx = t + l*256 -> row=idx>>2, c4=idx&3
    const int sr = t >> 2, sc4 = t & 3;

    auto stage = [&](int c, int buf) {
        const int k0 = c << 4;
#pragma unroll
        for (int l = 0; l < 2; ++l) {
            int row = sr + l * 64;
            cp_async16(smem_u32(&As[buf][row][sc4 * 4]),
                       A + (size_t)(m0 + row) * lda + k0 + sc4 * 4);
        }
#pragma unroll
        for (int l = 0; l < 2; ++l) {
            int row = sr + l * 64;
            cp_async16(smem_u32(&Bs[buf][row][sc4 * 4]),
                       B + (size_t)(n0 + row) * ldb + k0 + sc4 * 4);
        }
        CP_COMMIT();
    };

    stage(0, 0);

    for (int c = 0; c < nc; ++c) {
        const int buf = c & 1;
        if (c + 1 < nc) { stage(c + 1, buf ^ 1); CP_WAIT(1); }
        else            { CP_WAIT(0); }
        __syncthreads();

        const float* Ab = &As[buf][0][0];
        const float* Bb = &Bs[buf][0][0];
#pragma unroll
        for (int ks = 0; ks < 2; ++ks) {
            const int kc = ks * 8 + qid;
            uint32_t af[4][4], bf[4][2];
#pragma unroll
            for (int mi = 0; mi < 4; ++mi) {
                int r = wm + mi * 16 + grp;
                af[mi][0] = __float_as_uint(Ab[(size_t)r * BKP + kc]);
                af[mi][1] = __float_as_uint(Ab[(size_t)(r + 8) * BKP + kc]);
                af[mi][2] = __float_as_uint(Ab[(size_t)r * BKP + kc + 4]);
                af[mi][3] = __float_as_uint(Ab[(size_t)(r + 8) * BKP + kc + 4]);
            }
#pragma unroll
            for (int ni = 0; ni < 4; ++ni) {
                int r = wn + ni * 8 + grp;
                bf[ni][0] = __float_as_uint(Bb[(size_t)r * BKP + kc]);
                bf[ni][1] = __float_as_uint(Bb[(size_t)r * BKP + kc + 4]);
            }
#pragma unroll
            for (int mi = 0; mi < 4; ++mi)
#pragma unroll
                for (int ni = 0; ni < 4; ++ni)
                    mma_tf32(acc[mi][ni], af[mi], bf[ni]);
        }
        __syncthreads();
    }

    // epilogue: c0,c1 at (row, 2q..2q+1); c2,c3 at (row+8, same cols)
#pragma unroll
    for (int mi = 0; mi < 4; ++mi) {
#pragma unroll
        for (int ni = 0; ni < 4; ++ni) {
            int gm = m0 + wm + mi * 16 + grp;
            int gn = n0 + wn + ni * 8 + 2 * qid;
            float v0 = acc[mi][ni][0], v1 = acc[mi][ni][1];
            float v2 = acc[mi][ni][2], v3 = acc[mi][ni][3];
            if (epi == 1) {
                v0 = (gn     > gm)     ? -INFINITY : v0 * SCALING;
                v1 = (gn + 1 > gm)     ? -INFINITY : v1 * SCALING;
                v2 = (gn     > gm + 8) ? -INFINITY : v2 * SCALING;
                v3 = (gn + 1 > gm + 8) ? -INFINITY : v3 * SCALING;
            } else if (epi == 2) {
                v0 = rna_tf32(v0); v1 = rna_tf32(v1);
                v2 = rna_tf32(v2); v3 = rna_tf32(v3);
            }
            *(float2*)(C + (size_t)gm * ldc + gn)       = make_float2(v0, v1);
            *(float2*)(C + (size_t)(gm + 8) * ldc + gn) = make_float2(v2, v3);
        }
    }
}

// ---------------------------------------------------------------------------
// Elementwise tf32 rounding of hidden_states
// ---------------------------------------------------------------------------
__global__ __launch_bounds__(256) void k_round_hs(const float* __restrict__ in)
{
    size_t i = ((size_t)blockIdx.x * 256 + threadIdx.x) * 4;
    float4 v = *(const float4*)(in + i);
    v.x = rna_tf32(v.x); v.y = rna_tf32(v.y); v.z = rna_tf32(v.z); v.w = rna_tf32(v.w);
    *(float4*)(g_hs + i) = v;
}

// ---------------------------------------------------------------------------
// Transpose + round: out[n][k] = rna(in[k][n]); in is R x Cc
// ---------------------------------------------------------------------------
__global__ __launch_bounds__(256) void k_transpose_rna(
    const float* __restrict__ in, float* __restrict__ out, int R, int Cc)
{
    __shared__ float tile[32][33];
    int c0 = blockIdx.x * 32, r0 = blockIdx.y * 32;
    int x = threadIdx.x & 31, y = (threadIdx.x >> 5) * 4;
#pragma unroll
    for (int i = 0; i < 4; ++i)
        tile[y + i][x] = in[(size_t)(r0 + y + i) * Cc + c0 + x];
    __syncthreads();
#pragma unroll
    for (int i = 0; i < 4; ++i)
        out[(size_t)(c0 + y + i) * R + r0 + x] = rna_tf32(tile[x][y + i]);
}

// V transpose per (s,kv): g_vt[b][d][t] = rna(g_v[(s*SEQ+t)][kv*HD+d])
__global__ __launch_bounds__(256) void k_vtrans()
{
    __shared__ float tile[32][33];
    int b = blockIdx.z, s = b >> 2, kv = b & 3;
    const float* in = g_v + (size_t)s * SEQ * KD + kv * HD;
    float* out = g_vt + (size_t)b * HD * SEQ;
    int d0 = blockIdx.x * 32, t0 = blockIdx.y * 32;
    int x = threadIdx.x & 31, y = (threadIdx.x >> 5) * 4;
#pragma unroll
    for (int i = 0; i < 4; ++i)
        tile[y + i][x] = in[(size_t)(t0 + y + i) * KD + d0 + x];
    __syncthreads();
#pragma unroll
    for (int i = 0; i < 4; ++i)
        out[(size_t)(d0 + y + i) * SEQ + t0 + x] = rna_tf32(tile[x][y + i]);
}

// ---------------------------------------------------------------------------
// RMSNorm + RoPE, in place, output rounded to tf32
// ---------------------------------------------------------------------------
__device__ __forceinline__ void rmsrope_body(float* __restrict__ x,
                                             const float* __restrict__ w,
                                             const float* __restrict__ cosp,
                                             const float* __restrict__ sinp,
                                             int nh)
{
    int tok = blockIdx.x, h = blockIdx.y;
    float* p = x + ((size_t)tok * nh + h) * HD;
    int d = threadIdx.x;
    float v = p[d];
    float ssq = v * v;
#pragma unroll
    for (int o = 16; o > 0; o >>= 1) ssq += __shfl_xor_sync(0xffffffffu, ssq, o);
    __shared__ float ws[8];
    if ((d & 31) == 0) ws[d >> 5] = ssq;
    __syncthreads();
    float tot = 0.f;
#pragma unroll
    for (int i = 0; i < 8; i++) tot += ws[i];
    float r = rsqrtf(tot * (1.0f / HD) + EPS);
    float nv = v * r * (1.0f + w[d]);
    __shared__ float sn[HD];
    sn[d] = nv;
    __syncthreads();
    float rot = (d < HD / 2) ? -sn[d + HD / 2] : sn[d - HD / 2];
    p[d] = rna_tf32(nv * cosp[(size_t)tok * HD + d] + rot * sinp[(size_t)tok * HD + d]);
}
__global__ __launch_bounds__(256) void k_rope_q(const float* w, const float* c, const float* s)
{ rmsrope_body(g_q, w, c, s, NH); }
__global__ __launch_bounds__(256) void k_rope_k(const float* w, const float* c, const float* s)
{ rmsrope_body(g_k, w, c, s, NKV); }

// ---------------------------------------------------------------------------
// Row softmax over 1024 entries; output rounded to tf32
// ---------------------------------------------------------------------------
__global__ __launch_bounds__(256) void k_softmax()
{
    float* row = g_scores + (size_t)blockIdx.x * SEQ;
    int d = threadIdx.x;
    float4 v = *(float4*)(row + d * 4);
    float m = fmaxf(fmaxf(v.x, v.y), fmaxf(v.z, v.w));
#pragma unroll
    for (int o = 16; o > 0; o >>= 1) m = fmaxf(m, __shfl_xor_sync(0xffffffffu, m, o));
    __shared__ float wm[8];
    if ((d & 31) == 0) wm[d >> 5] = m;
    __syncthreads();
    float gm = wm[0];
#pragma unroll
    for (int i = 1; i < 8; i++) gm = fmaxf(gm, wm[i]);
    v.x = __expf(v.x - gm); v.y = __expf(v.y - gm);
    v.z = __expf(v.z - gm); v.w = __expf(v.w - gm);
    float ssum = v.x + v.y + v.z + v.w;
#pragma unroll
    for (int o = 16; o > 0; o >>= 1) ssum += __shfl_xor_sync(0xffffffffu, ssum, o);
    __shared__ float wsum[8];
    if ((d & 31) == 0) wsum[d >> 5] = ssum;
    __syncthreads();
    float tot = 0.f;
#pragma unroll
    for (int i = 0; i < 8; i++) tot += wsum[i];
    float inv = 1.0f / tot;
    v.x = rna_tf32(v.x * inv); v.y = rna_tf32(v.y * inv);
    v.z = rna_tf32(v.z * inv); v.w = rna_tf32(v.w * inv);
    *(float4*)(row + d * 4) = v;
}

// ---------------------------------------------------------------------------
// kernel_launch
// inputs: hidden_states, cos, sin, Wq, Wk, Wv, Wo, q_norm_w, k_norm_w, cu_seqlens
// ---------------------------------------------------------------------------
extern "C" void kernel_launch(void* const* d_in, const int* in_sizes, int n_in,
                              void* d_out, int out_size)
{
    const float* hs   = (const float*)d_in[0];
    const float* cosp = (const float*)d_in[1];
    const float* sinp = (const float*)d_in[2];
    const float* Wq   = (const float*)d_in[3];
    const float* Wk   = (const float*)d_in[4];
    const float* Wv   = (const float*)d_in[5];
    const float* Wo   = (const float*)d_in[6];
    const float* qw   = (const float*)d_in[7];
    const float* kw   = (const float*)d_in[8];
    float* out = (float*)d_out;

    float *p_hs, *p_WqT, *p_WkT, *p_WvT, *p_WoT, *p_q, *p_k, *p_v, *p_attn;
    cudaGetSymbolAddress((void**)&p_hs,  g_hs);
    cudaGetSymbolAddress((void**)&p_WqT, g_WqT);
    cudaGetSymbolAddress((void**)&p_WkT, g_WkT);
    cudaGetSymbolAddress((void**)&p_WvT, g_WvT);
    cudaGetSymbolAddress((void**)&p_WoT, g_WoT);
    cudaGetSymbolAddress((void**)&p_q,   g_q);
    cudaGetSymbolAddress((void**)&p_k,   g_k);
    cudaGetSymbolAddress((void**)&p_v,   g_v);
    cudaGetSymbolAddress((void**)&p_attn, g_attn);

    dim3 thr(256);

    // 1) round hidden states, transpose+round weights
    k_round_hs<<<(L_TOT * HID) / 1024, thr>>>(hs);
    k_transpose_rna<<<dim3(QD / 32, HID / 32), thr>>>(Wq, p_WqT, HID, QD);
    k_transpose_rna<<<dim3(KD / 32, HID / 32), thr>>>(Wk, p_WkT, HID, KD);
    k_transpose_rna<<<dim3(KD / 32, HID / 32), thr>>>(Wv, p_WvT, HID, KD);
    k_transpose_rna<<<dim3(HID / 32, QD / 32), thr>>>(Wo, p_WoT, QD, HID);

    // 2) projections
    k_gemm<<<dim3(QD / BN, L_TOT / BM), thr>>>(p_hs, p_WqT, p_q, HID, HID, QD, HID, 0, 0);
    k_gemm<<<dim3(KD / BN, L_TOT / BM), thr>>>(p_hs, p_WkT, p_k, HID, HID, KD, HID, 0, 0);
    k_gemm<<<dim3(KD / BN, L_TOT / BM), thr>>>(p_hs, p_WvT, p_v, HID, HID, KD, HID, 0, 0);

    // 3) norm + rope (rounds q,k); V transpose (rounds v)
    k_rope_q<<<dim3(L_TOT, NH),  thr>>>(qw, cosp, sinp);
    k_rope_k<<<dim3(L_TOT, NKV), thr>>>(kw, cosp, sinp);
    k_vtrans<<<dim3(HD / 32, SEQ / 32, NSEQ * NKV), thr>>>();

    // 4) scores (scale+mask), softmax (rounds), PV (rounds)
    k_gemm<<<dim3(SEQ / BN, SEQ / BM, NH * NSEQ), thr>>>(
        nullptr, nullptr, nullptr, 0, 0, 0, HD, 1, 1);
    k_softmax<<<NH * L_TOT, thr>>>();
    k_gemm<<<dim3(HD / BN, SEQ / BM, NH * NSEQ), thr>>>(
        nullptr, nullptr, nullptr, 0, 0, 0, SEQ, 2, 2);

    // 5) output projection
    k_gemm<<<dim3(HID / BN, L_TOT / BM), thr>>>(p_attn, p_WoT, out, QD, QD, HID, QD, 0, 0);
}

// round 6
// speedup vs baseline: 4.5303x; 1.8950x over previous
#include <cuda_runtime.h>
#include <cuda_fp16.h>
#include <math.h>
#include <stdint.h>

// ---------------------------------------------------------------------------
// Problem constants
// ---------------------------------------------------------------------------
#define L_TOT   4096
#define HID     2560
#define NH      8
#define NKV     4
#define HD      256
#define QD      (NH*HD)    // 2048
#define KD      (NKV*HD)   // 1024
#define SEQ     1024
#define NSEQ    4
#define SCALING 0.0625f
#define EPS     1e-6f

// ---------------------------------------------------------------------------
// Scratch (__device__ globals)
// ---------------------------------------------------------------------------
__device__ __half g_hs16 [(size_t)L_TOT * HID];
__device__ __half g_WqT16[(size_t)QD * HID];
__device__ __half g_WkT16[(size_t)KD * HID];
__device__ __half g_WvT16[(size_t)KD * HID];
__device__ __half g_WoT16[(size_t)HID * QD];
__device__ float  g_q    [(size_t)L_TOT * QD];   // proj out (pre-rope)
__device__ float  g_k    [(size_t)L_TOT * KD];
__device__ float  g_v    [(size_t)L_TOT * KD];
__device__ __half g_q16  [(size_t)L_TOT * QD];   // post rope (scaled)
__device__ __half g_k16  [(size_t)L_TOT * KD];
__device__ __half g_vt16 [(size_t)NSEQ * NKV * HD * SEQ]; // [d][t]
__device__ float  g_scores[(size_t)NH * L_TOT * SEQ];
__device__ __half g_p16  [(size_t)NH * L_TOT * SEQ];
__device__ __half g_attn16[(size_t)L_TOT * QD];

// ---------------------------------------------------------------------------
// Helpers
// ---------------------------------------------------------------------------
__device__ __forceinline__ uint32_t smem_u32(const void* p) {
    uint32_t a;
    asm("{ .reg .u64 t; cvta.to.shared.u64 t, %1; cvt.u32.u64 %0, t; }"
        : "=r"(a) : "l"(p));
    return a;
}
__device__ __forceinline__ void cp_async16(uint32_t dst, const void* src) {
    asm volatile("cp.async.ca.shared.global [%0], [%1], 16;" :: "r"(dst), "l"(src));
}
#define CP_COMMIT()  asm volatile("cp.async.commit_group;" ::: "memory")
#define CP_WAIT(n)   asm volatile("cp.async.wait_group %0;" :: "n"(n) : "memory")

// mma.sync m16n8k16 fp16 -> fp32
__device__ __forceinline__ void mma_f16(float* c, const uint32_t* a, const uint32_t* b) {
    asm volatile(
        "mma.sync.aligned.m16n8k16.row.col.f32.f16.f16.f32 "
        "{%0,%1,%2,%3}, {%4,%5,%6,%7}, {%8,%9}, {%0,%1,%2,%3};"
        : "+f"(c[0]), "+f"(c[1]), "+f"(c[2]), "+f"(c[3])
        : "r"(a[0]), "r"(a[1]), "r"(a[2]), "r"(a[3]), "r"(b[0]), "r"(b[1]));
}

// ---------------------------------------------------------------------------
// fp16 mma.sync GEMM: C(MxN) = A(MxK) * B(NxK)^T
// CTA 128x128, BK=32 halves, 256 thr (8 warps 2x4), warp tile 64x32.
// mode: 0=plain, 1=scores, 2=pv.   epi: 0=f32 store, 1=mask+f32, 2=half store
// ---------------------------------------------------------------------------
#define BM 128
#define BN 128
#define BK 32
#define SKP 40   // smem row stride in halves (80 B, 16B-multiple, conflict-free)

__global__ __launch_bounds__(256) void k_gemm16(
    const __half* __restrict__ A, const __half* __restrict__ B, void* __restrict__ Cv,
    int lda, int ldb, int ldc, int K, int mode, int epi)
{
    const int t    = threadIdx.x;
    const int lane = t & 31;
    const int wid  = t >> 5;
    const int grp  = lane >> 2;
    const int qid  = lane & 3;
    const int wm   = (wid >> 2) * 64;
    const int wn   = (wid & 3) * 32;
    const int m0   = blockIdx.y * BM;
    const int n0   = blockIdx.x * BN;

    float* Cf = (float*)Cv;
    __half* Ch = (__half*)Cv;

    if (mode == 1) {
        int h = blockIdx.z >> 2, s = blockIdx.z & 3;
        A  = g_q16 + (size_t)s * SEQ * QD + h * HD;                  lda = QD;
        B  = g_k16 + (size_t)s * SEQ * KD + (h >> 1) * HD;           ldb = KD;
        Cf = g_scores + ((size_t)h * L_TOT + (size_t)s * SEQ) * SEQ; ldc = SEQ;
    } else if (mode == 2) {
        int h = blockIdx.z >> 2, s = blockIdx.z & 3;
        A  = g_p16 + ((size_t)h * L_TOT + (size_t)s * SEQ) * SEQ;    lda = SEQ;
        B  = g_vt16 + ((size_t)(s * NKV + (h >> 1))) * HD * SEQ;     ldb = SEQ;
        Ch = g_attn16 + (size_t)s * SEQ * QD + h * HD;               ldc = QD;
    }

    // fully above causal diagonal: -inf fill, skip
    if (epi == 1 && n0 > m0 + (BM - 1)) {
        const float4 ninf = make_float4(-INFINITY, -INFINITY, -INFINITY, -INFINITY);
#pragma unroll
        for (int l = 0; l < 16; ++l) {
            int idx = t + (l << 8);
            int r = idx >> 5, c4 = idx & 31;
            *(float4*)(Cf + (size_t)(m0 + r) * ldc + n0 + (c4 << 2)) = ninf;
        }
        return;
    }

    __shared__ __half As[2][BM][SKP];
    __shared__ __half Bs[2][BN][SKP];

    float acc[4][4][4];
#pragma unroll
    for (int mi = 0; mi < 4; ++mi)
#pragma unroll
        for (int ni = 0; ni < 4; ++ni)
#pragma unroll
            for (int q = 0; q < 4; ++q) acc[mi][ni][q] = 0.f;

    int nc = K >> 5;
    if (mode == 2) {                        // causal clamp: P==0 beyond row
        int lim = (m0 + BM) >> 5;
        if (lim < nc) nc = lim;
    }

    auto stage = [&](int c, int buf) {
        const int k0 = c << 5;
#pragma unroll
        for (int l = 0; l < 2; ++l) {
            int slot = t + (l << 8);
            int row = slot >> 2, seg = slot & 3;
            cp_async16(smem_u32(&As[buf][row][seg * 8]),
                       A + (size_t)(m0 + row) * lda + k0 + seg * 8);
        }
#pragma unroll
        for (int l = 0; l < 2; ++l) {
            int slot = t + (l << 8);
            int row = slot >> 2, seg = slot & 3;
            cp_async16(smem_u32(&Bs[buf][row][seg * 8]),
                       B + (size_t)(n0 + row) * ldb + k0 + seg * 8);
        }
        CP_COMMIT();
    };

    stage(0, 0);

    for (int c = 0; c < nc; ++c) {
        const int buf = c & 1;
        if (c + 1 < nc) { stage(c + 1, buf ^ 1); CP_WAIT(1); }
        else            { CP_WAIT(0); }
        __syncthreads();

        const __half* Ab = &As[buf][0][0];
        const __half* Bb = &Bs[buf][0][0];
#pragma unroll
        for (int ks = 0; ks < 2; ++ks) {
            const int kc = ks * 16 + 2 * qid;
            uint32_t au[4][4], bu[4][2];
#pragma unroll
            for (int mi = 0; mi < 4; ++mi) {
                int r = wm + mi * 16 + grp;
                au[mi][0] = *(const uint32_t*)&Ab[(size_t)r * SKP + kc];
                au[mi][1] = *(const uint32_t*)&Ab[(size_t)(r + 8) * SKP + kc];
                au[mi][2] = *(const uint32_t*)&Ab[(size_t)r * SKP + kc + 8];
                au[mi][3] = *(const uint32_t*)&Ab[(size_t)(r + 8) * SKP + kc + 8];
            }
#pragma unroll
            for (int ni = 0; ni < 4; ++ni) {
                int r = wn + ni * 8 + grp;
                bu[ni][0] = *(const uint32_t*)&Bb[(size_t)r * SKP + kc];
                bu[ni][1] = *(const uint32_t*)&Bb[(size_t)r * SKP + kc + 8];
            }
#pragma unroll
            for (int mi = 0; mi < 4; ++mi)
#pragma unroll
                for (int ni = 0; ni < 4; ++ni)
                    mma_f16(acc[mi][ni], au[mi], bu[ni]);
        }
        __syncthreads();
    }

    // epilogue
#pragma unroll
    for (int mi = 0; mi < 4; ++mi) {
#pragma unroll
        for (int ni = 0; ni < 4; ++ni) {
            int gm = m0 + wm + mi * 16 + grp;
            int gn = n0 + wn + ni * 8 + 2 * qid;
            float v0 = acc[mi][ni][0], v1 = acc[mi][ni][1];
            float v2 = acc[mi][ni][2], v3 = acc[mi][ni][3];
            if (epi == 1) {
                v0 = (gn     > gm)     ? -INFINITY : v0;
                v1 = (gn + 1 > gm)     ? -INFINITY : v1;
                v2 = (gn     > gm + 8) ? -INFINITY : v2;
                v3 = (gn + 1 > gm + 8) ? -INFINITY : v3;
                *(float2*)(Cf + (size_t)gm * ldc + gn)       = make_float2(v0, v1);
                *(float2*)(Cf + (size_t)(gm + 8) * ldc + gn) = make_float2(v2, v3);
            } else if (epi == 2) {
                *(__half2*)(Ch + (size_t)gm * ldc + gn)       = __floats2half2_rn(v0, v1);
                *(__half2*)(Ch + (size_t)(gm + 8) * ldc + gn) = __floats2half2_rn(v2, v3);
            } else {
                *(float2*)(Cf + (size_t)gm * ldc + gn)       = make_float2(v0, v1);
                *(float2*)(Cf + (size_t)(gm + 8) * ldc + gn) = make_float2(v2, v3);
            }
        }
    }
}

// ---------------------------------------------------------------------------
// hidden_states fp32 -> fp16
// ---------------------------------------------------------------------------
__global__ __launch_bounds__(256) void k_cvt_hs(const float* __restrict__ in)
{
    size_t i = ((size_t)blockIdx.x * 256 + threadIdx.x) * 4;
    float4 v = *(const float4*)(in + i);
    *(__half2*)(g_hs16 + i)     = __floats2half2_rn(v.x, v.y);
    *(__half2*)(g_hs16 + i + 2) = __floats2half2_rn(v.z, v.w);
}

// ---------------------------------------------------------------------------
// Transpose + cvt: out(half)[n][k] = in(f32)[k][n]; in is R x Cc
// ---------------------------------------------------------------------------
__global__ __launch_bounds__(256) void k_transpose_h(
    const float* __restrict__ in, __half* __restrict__ out, int R, int Cc)
{
    __shared__ float tile[32][33];
    int c0 = blockIdx.x * 32, r0 = blockIdx.y * 32;
    int x = threadIdx.x & 31, y = (threadIdx.x >> 5) * 4;
#pragma unroll
    for (int i = 0; i < 4; ++i)
        tile[y + i][x] = in[(size_t)(r0 + y + i) * Cc + c0 + x];
    __syncthreads();
#pragma unroll
    for (int i = 0; i < 4; ++i)
        out[(size_t)(c0 + y + i) * R + r0 + x] = __float2half_rn(tile[x][y + i]);
}

// V transpose per (s,kv): g_vt16[b][d][t] = half(g_v[(s*SEQ+t)][kv*HD+d])
__global__ __launch_bounds__(256) void k_vtrans()
{
    __shared__ float tile[32][33];
    int b = blockIdx.z, s = b >> 2, kv = b & 3;
    const float* in = g_v + (size_t)s * SEQ * KD + kv * HD;
    __half* out = g_vt16 + (size_t)b * HD * SEQ;
    int d0 = blockIdx.x * 32, t0 = blockIdx.y * 32;
    int x = threadIdx.x & 31, y = (threadIdx.x >> 5) * 4;
#pragma unroll
    for (int i = 0; i < 4; ++i)
        tile[y + i][x] = in[(size_t)(t0 + y + i) * KD + d0 + x];
    __syncthreads();
#pragma unroll
    for (int i = 0; i < 4; ++i)
        out[(size_t)(d0 + y + i) * SEQ + t0 + x] = __float2half_rn(tile[x][y + i]);
}

// ---------------------------------------------------------------------------
// RMSNorm + RoPE; q additionally scaled by SCALING; outputs fp16.
// ---------------------------------------------------------------------------
__device__ __forceinline__ void rmsrope_body(const float* __restrict__ x,
                                             __half* __restrict__ y,
                                             const float* __restrict__ w,
                                             const float* __restrict__ cosp,
                                             const float* __restrict__ sinp,
                                             int nh, float post_scale)
{
    int tok = blockIdx.x, h = blockIdx.y;
    const float* p = x + ((size_t)tok * nh + h) * HD;
    __half* o = y + ((size_t)tok * nh + h) * HD;
    int d = threadIdx.x;
    float v = p[d];
    float ssq = v * v;
#pragma unroll
    for (int off = 16; off > 0; off >>= 1) ssq += __shfl_xor_sync(0xffffffffu, ssq, off);
    __shared__ float ws[8];
    if ((d & 31) == 0) ws[d >> 5] = ssq;
    __syncthreads();
    float tot = 0.f;
#pragma unroll
    for (int i = 0; i < 8; i++) tot += ws[i];
    float r = rsqrtf(tot * (1.0f / HD) + EPS);
    float nv = v * r * (1.0f + w[d]);
    __shared__ float sn[HD];
    sn[d] = nv;
    __syncthreads();
    float rot = (d < HD / 2) ? -sn[d + HD / 2] : sn[d - HD / 2];
    float res = (nv * cosp[(size_t)tok * HD + d] + rot * sinp[(size_t)tok * HD + d]) * post_scale;
    o[d] = __float2half_rn(res);
}
__global__ __launch_bounds__(256) void k_rope_q(const float* w, const float* c, const float* s)
{ rmsrope_body(g_q, g_q16, w, c, s, NH, SCALING); }
__global__ __launch_bounds__(256) void k_rope_k(const float* w, const float* c, const float* s)
{ rmsrope_body(g_k, g_k16, w, c, s, NKV, 1.0f); }

// ---------------------------------------------------------------------------
// Row softmax over 1024 fp32 scores -> fp16 P
// ---------------------------------------------------------------------------
__global__ __launch_bounds__(256) void k_softmax()
{
    const float* row = g_scores + (size_t)blockIdx.x * SEQ;
    __half* prow = g_p16 + (size_t)blockIdx.x * SEQ;
    int d = threadIdx.x;
    float4 v = *(const float4*)(row + d * 4);
    float m = fmaxf(fmaxf(v.x, v.y), fmaxf(v.z, v.w));
#pragma unroll
    for (int o = 16; o > 0; o >>= 1) m = fmaxf(m, __shfl_xor_sync(0xffffffffu, m, o));
    __shared__ float wm[8];
    if ((d & 31) == 0) wm[d >> 5] = m;
    __syncthreads();
    float gm = wm[0];
#pragma unroll
    for (int i = 1; i < 8; i++) gm = fmaxf(gm, wm[i]);
    v.x = __expf(v.x - gm); v.y = __expf(v.y - gm);
    v.z = __expf(v.z - gm); v.w = __expf(v.w - gm);
    float ssum = v.x + v.y + v.z + v.w;
#pragma unroll
    for (int o = 16; o > 0; o >>= 1) ssum += __shfl_xor_sync(0xffffffffu, ssum, o);
    __shared__ float wsum[8];
    if ((d & 31) == 0) wsum[d >> 5] = ssum;
    __syncthreads();
    float tot = 0.f;
#pragma unroll
    for (int i = 0; i < 8; i++) tot += wsum[i];
    float inv = 1.0f / tot;
    *(__half2*)(prow + d * 4)     = __floats2half2_rn(v.x * inv, v.y * inv);
    *(__half2*)(prow + d * 4 + 2) = __floats2half2_rn(v.z * inv, v.w * inv);
}

// ---------------------------------------------------------------------------
// kernel_launch
// inputs: hidden_states, cos, sin, Wq, Wk, Wv, Wo, q_norm_w, k_norm_w, cu_seqlens
// ---------------------------------------------------------------------------
extern "C" void kernel_launch(void* const* d_in, const int* in_sizes, int n_in,
                              void* d_out, int out_size)
{
    const float* hs   = (const float*)d_in[0];
    const float* cosp = (const float*)d_in[1];
    const float* sinp = (const float*)d_in[2];
    const float* Wq   = (const float*)d_in[3];
    const float* Wk   = (const float*)d_in[4];
    const float* Wv   = (const float*)d_in[5];
    const float* Wo   = (const float*)d_in[6];
    const float* qw   = (const float*)d_in[7];
    const float* kw   = (const float*)d_in[8];
    float* out = (float*)d_out;

    __half *p_hs16, *p_WqT16, *p_WkT16, *p_WvT16, *p_WoT16, *p_attn16;
    float  *p_q, *p_k, *p_v;
    cudaGetSymbolAddress((void**)&p_hs16,   g_hs16);
    cudaGetSymbolAddress((void**)&p_WqT16,  g_WqT16);
    cudaGetSymbolAddress((void**)&p_WkT16,  g_WkT16);
    cudaGetSymbolAddress((void**)&p_WvT16,  g_WvT16);
    cudaGetSymbolAddress((void**)&p_WoT16,  g_WoT16);
    cudaGetSymbolAddress((void**)&p_attn16, g_attn16);
    cudaGetSymbolAddress((void**)&p_q, g_q);
    cudaGetSymbolAddress((void**)&p_k, g_k);
    cudaGetSymbolAddress((void**)&p_v, g_v);

    dim3 thr(256);

    // 1) convert hidden states; transpose+convert weights
    k_cvt_hs<<<(L_TOT * HID) / 1024, thr>>>(hs);
    k_transpose_h<<<dim3(QD / 32, HID / 32), thr>>>(Wq, p_WqT16, HID, QD);
    k_transpose_h<<<dim3(KD / 32, HID / 32), thr>>>(Wk, p_WkT16, HID, KD);
    k_transpose_h<<<dim3(KD / 32, HID / 32), thr>>>(Wv, p_WvT16, HID, KD);
    k_transpose_h<<<dim3(HID / 32, QD / 32), thr>>>(Wo, p_WoT16, QD, HID);

    // 2) projections (fp16 in, fp32 out)
    k_gemm16<<<dim3(QD / BN, L_TOT / BM), thr>>>(p_hs16, p_WqT16, p_q, HID, HID, QD, HID, 0, 0);
    k_gemm16<<<dim3(KD / BN, L_TOT / BM), thr>>>(p_hs16, p_WkT16, p_k, HID, HID, KD, HID, 0, 0);
    k_gemm16<<<dim3(KD / BN, L_TOT / BM), thr>>>(p_hs16, p_WvT16, p_v, HID, HID, KD, HID, 0, 0);

    // 3) norm+rope (fp16 out, q pre-scaled); V transpose (fp16 out)
    k_rope_q<<<dim3(L_TOT, NH),  thr>>>(qw, cosp, sinp);
    k_rope_k<<<dim3(L_TOT, NKV), thr>>>(kw, cosp, sinp);
    k_vtrans<<<dim3(HD / 32, SEQ / 32, NSEQ * NKV), thr>>>();

    // 4) scores (mask), softmax (fp16 P), PV (causal-clamped, fp16 out)
    k_gemm16<<<dim3(SEQ / BN, SEQ / BM, NH * NSEQ), thr>>>(
        nullptr, nullptr, nullptr, 0, 0, 0, HD, 1, 1);
    k_softmax<<<NH * L_TOT, thr>>>();
    k_gemm16<<<dim3(HD / BN, SEQ / BM, NH * NSEQ), thr>>>(
        nullptr, nullptr, nullptr, 0, 0, 0, SEQ, 2, 2);

    // 5) output projection (fp32 out to d_out)
    k_gemm16<<<dim3(HID / BN, L_TOT / BM), thr>>>(p_attn16, p_WoT16, out, QD, QD, HID, QD, 0, 0);
}

// round 7
// speedup vs baseline: 5.2081x; 1.1496x over previous
#include <cuda_runtime.h>
#include <cuda_fp16.h>
#include <math.h>
#include <stdint.h>

// ---------------------------------------------------------------------------
// Problem constants
// ---------------------------------------------------------------------------
#define L_TOT   4096
#define HID     2560
#define NH      8
#define NKV     4
#define HD      256
#define QD      (NH*HD)    // 2048
#define KD      (NKV*HD)   // 1024
#define SEQ     1024
#define NSEQ    4
#define SCALING 0.0625f
#define EPS     1e-6f

// ---------------------------------------------------------------------------
// Scratch (__device__ globals)
// ---------------------------------------------------------------------------
__device__ __half g_hs16 [(size_t)L_TOT * HID];
__device__ __half g_WqT16[(size_t)QD * HID];
__device__ __half g_WkT16[(size_t)KD * HID];
__device__ __half g_WvT16[(size_t)KD * HID];
__device__ __half g_WoT16[(size_t)HID * QD];
__device__ float  g_q    [(size_t)L_TOT * QD];
__device__ float  g_k    [(size_t)L_TOT * KD];
__device__ float  g_v    [(size_t)L_TOT * KD];
__device__ __half g_q16  [(size_t)L_TOT * QD];
__device__ __half g_k16  [(size_t)L_TOT * KD];
__device__ __half g_vt16 [(size_t)NSEQ * NKV * HD * SEQ]; // [d][t]
__device__ float  g_scores[(size_t)NH * L_TOT * SEQ];
__device__ __half g_p16  [(size_t)NH * L_TOT * SEQ];
__device__ __half g_attn16[(size_t)L_TOT * QD];

// ---------------------------------------------------------------------------
// Helpers
// ---------------------------------------------------------------------------
__device__ __forceinline__ uint32_t smem_u32(const void* p) {
    uint32_t a;
    asm("{ .reg .u64 t; cvta.to.shared.u64 t, %1; cvt.u32.u64 %0, t; }"
        : "=r"(a) : "l"(p));
    return a;
}
__device__ __forceinline__ void cp_async16(uint32_t dst, const void* src) {
    asm volatile("cp.async.ca.shared.global [%0], [%1], 16;" :: "r"(dst), "l"(src));
}
#define CP_COMMIT()  asm volatile("cp.async.commit_group;" ::: "memory")
#define CP_WAIT(n)   asm volatile("cp.async.wait_group %0;" :: "n"(n) : "memory")

__device__ __forceinline__ void ldsm_x4(uint32_t* d, uint32_t addr) {
    asm volatile("ldmatrix.sync.aligned.m8n8.x4.shared.b16 {%0,%1,%2,%3}, [%4];"
                 : "=r"(d[0]), "=r"(d[1]), "=r"(d[2]), "=r"(d[3]) : "r"(addr));
}

// mma.sync m16n8k16 fp16 -> fp32
__device__ __forceinline__ void mma_f16(float* c, const uint32_t* a, const uint32_t* b) {
    asm volatile(
        "mma.sync.aligned.m16n8k16.row.col.f32.f16.f16.f32 "
        "{%0,%1,%2,%3}, {%4,%5,%6,%7}, {%8,%9}, {%0,%1,%2,%3};"
        : "+f"(c[0]), "+f"(c[1]), "+f"(c[2]), "+f"(c[3])
        : "r"(a[0]), "r"(a[1]), "r"(a[2]), "r"(a[3]), "r"(b[0]), "r"(b[1]));
}

// ---------------------------------------------------------------------------
// fp16 mma.sync GEMM: C(MxN) = A(MxK) * B(NxK)^T
// CTA 128x128, BK=32 halves, 3-stage cp.async, ldmatrix fragments.
// 256 thr (8 warps 2x4), warp tile 64x32.
// mode: 0=plain, 1=scores, 2=pv.  epi: 0=f32, 1=mask+f32, 2=half
// ---------------------------------------------------------------------------
#define BM 128
#define BN 128
#define BK 32
#define SKP 40                      // smem row stride in halves
#define STG_H (BM * SKP)            // halves per A (or B) stage = 5120
#define SMEM_DYN (6 * STG_H * 2)    // 3 stages x (A+B) = 61440 B

__global__ __launch_bounds__(256, 2) void k_gemm16(
    const __half* __restrict__ A, const __half* __restrict__ B, void* __restrict__ Cv,
    int lda, int ldb, int ldc, int K, int mode, int epi)
{
    const int t    = threadIdx.x;
    const int lane = t & 31;
    const int wid  = t >> 5;
    const int grp  = lane >> 2;
    const int qid  = lane & 3;
    const int wm   = (wid >> 2) * 64;
    const int wn   = (wid & 3) * 32;
    const int m0   = blockIdx.y * BM;
    const int n0   = blockIdx.x * BN;

    float* Cf = (float*)Cv;
    __half* Ch = (__half*)Cv;

    if (mode == 1) {
        int h = blockIdx.z >> 2, s = blockIdx.z & 3;
        A  = g_q16 + (size_t)s * SEQ * QD + h * HD;                  lda = QD;
        B  = g_k16 + (size_t)s * SEQ * KD + (h >> 1) * HD;           ldb = KD;
        Cf = g_scores + ((size_t)h * L_TOT + (size_t)s * SEQ) * SEQ; ldc = SEQ;
    } else if (mode == 2) {
        int h = blockIdx.z >> 2, s = blockIdx.z & 3;
        A  = g_p16 + ((size_t)h * L_TOT + (size_t)s * SEQ) * SEQ;    lda = SEQ;
        B  = g_vt16 + ((size_t)(s * NKV + (h >> 1))) * HD * SEQ;     ldb = SEQ;
        Ch = g_attn16 + (size_t)s * SEQ * QD + h * HD;               ldc = QD;
    }

    // fully above causal diagonal: softmax masks by index now -> nothing to do
    if (epi == 1 && n0 > m0 + (BM - 1)) return;

    extern __shared__ __half sm[];
    const uint32_t base = smem_u32(sm);

    float acc[4][4][4];
#pragma unroll
    for (int mi = 0; mi < 4; ++mi)
#pragma unroll
        for (int ni = 0; ni < 4; ++ni)
#pragma unroll
            for (int q = 0; q < 4; ++q) acc[mi][ni][q] = 0.f;

    int nc = K >> 5;
    if (mode == 2) {                       // causal clamp: P==0 beyond row band
        int lim = (m0 + BM) >> 5;
        if (lim < nc) nc = lim;
    }

    // staging coords: 512 slots = 128 rows x 4 segs (A), same for B
    const int srow = t >> 2, sseg = t & 3;

    auto stage = [&](int c, int s) {
        const int k0 = c << 5;
        const uint32_t offA = base + (uint32_t)(s * STG_H) * 2;
        const uint32_t offB = base + (uint32_t)((3 + s) * STG_H) * 2;
#pragma unroll
        for (int l = 0; l < 2; ++l) {
            int row = srow + l * 64;
            cp_async16(offA + (uint32_t)(row * SKP + sseg * 8) * 2,
                       A + (size_t)(m0 + row) * lda + k0 + sseg * 8);
        }
#pragma unroll
        for (int l = 0; l < 2; ++l) {
            int row = srow + l * 64;
            cp_async16(offB + (uint32_t)(row * SKP + sseg * 8) * 2,
                       B + (size_t)(n0 + row) * ldb + k0 + sseg * 8);
        }
        CP_COMMIT();
    };

    // per-lane ldmatrix byte offsets (within a stage)
    // A: row = wm + mi*16 + (lane&15), col = ks*16 + ((lane&16)?8:0)
    const uint32_t aRow = wm + (lane & 15);
    const uint32_t aCol = (lane & 16) ? 8u : 0u;
    const uint32_t aOffBase = (aRow * SKP + aCol) * 2;
    // B (pair p covers ni=2p, 2p+1): row = wn + p*16 + (lane&7) + ((lane&16)?8:0),
    //                                col = ks*16 + ((lane&8)?8:0)
    const uint32_t bRow = wn + (lane & 7) + ((lane & 16) ? 8u : 0u);
    const uint32_t bCol = (lane & 8) ? 8u : 0u;
    const uint32_t bOffBase = (bRow * SKP + bCol) * 2;

    stage(0, 0);
    if (nc > 1) stage(1, 1);

    for (int c = 0; c < nc; ++c) {
        const int s = c % 3;
        if (c + 2 < nc) { stage(c + 2, (c + 2) % 3); CP_WAIT(2); }
        else if (c + 1 < nc) { CP_WAIT(1); }
        else { CP_WAIT(0); }
        __syncthreads();

        const uint32_t uA = base + (uint32_t)(s * STG_H) * 2 + aOffBase;
        const uint32_t uB = base + (uint32_t)((3 + s) * STG_H) * 2 + bOffBase;

#pragma unroll
        for (int ks = 0; ks < 2; ++ks) {
            uint32_t au[4][4], bu[2][4];
#pragma unroll
            for (int mi = 0; mi < 4; ++mi)
                ldsm_x4(au[mi], uA + (uint32_t)(mi * 16 * SKP + ks * 16) * 2);
#pragma unroll
            for (int p = 0; p < 2; ++p)
                ldsm_x4(bu[p], uB + (uint32_t)(p * 16 * SKP + ks * 16) * 2);
#pragma unroll
            for (int mi = 0; mi < 4; ++mi)
#pragma unroll
                for (int ni = 0; ni < 4; ++ni)
                    mma_f16(acc[mi][ni], au[mi], &bu[ni >> 1][(ni & 1) * 2]);
        }
        __syncthreads();
    }

    // epilogue
#pragma unroll
    for (int mi = 0; mi < 4; ++mi) {
#pragma unroll
        for (int ni = 0; ni < 4; ++ni) {
            int gm = m0 + wm + mi * 16 + grp;
            int gn = n0 + wn + ni * 8 + 2 * qid;
            float v0 = acc[mi][ni][0], v1 = acc[mi][ni][1];
            float v2 = acc[mi][ni][2], v3 = acc[mi][ni][3];
            if (epi == 1) {
                v0 = (gn     > gm)     ? -INFINITY : v0;
                v1 = (gn + 1 > gm)     ? -INFINITY : v1;
                v2 = (gn     > gm + 8) ? -INFINITY : v2;
                v3 = (gn + 1 > gm + 8) ? -INFINITY : v3;
                *(float2*)(Cf + (size_t)gm * ldc + gn)       = make_float2(v0, v1);
                *(float2*)(Cf + (size_t)(gm + 8) * ldc + gn) = make_float2(v2, v3);
            } else if (epi == 2) {
                *(__half2*)(Ch + (size_t)gm * ldc + gn)       = __floats2half2_rn(v0, v1);
                *(__half2*)(Ch + (size_t)(gm + 8) * ldc + gn) = __floats2half2_rn(v2, v3);
            } else {
                *(float2*)(Cf + (size_t)gm * ldc + gn)       = make_float2(v0, v1);
                *(float2*)(Cf + (size_t)(gm + 8) * ldc + gn) = make_float2(v2, v3);
            }
        }
    }
}

// ---------------------------------------------------------------------------
// hidden_states fp32 -> fp16
// ---------------------------------------------------------------------------
__global__ __launch_bounds__(256) void k_cvt_hs(const float* __restrict__ in)
{
    size_t i = ((size_t)blockIdx.x * 256 + threadIdx.x) * 4;
    float4 v = *(const float4*)(in + i);
    *(__half2*)(g_hs16 + i)     = __floats2half2_rn(v.x, v.y);
    *(__half2*)(g_hs16 + i + 2) = __floats2half2_rn(v.z, v.w);
}

// ---------------------------------------------------------------------------
// Transpose + cvt: out(half)[n][k] = in(f32)[k][n]; in is R x Cc
// ---------------------------------------------------------------------------
__global__ __launch_bounds__(256) void k_transpose_h(
    const float* __restrict__ in, __half* __restrict__ out, int R, int Cc)
{
    __shared__ float tile[32][33];
    int c0 = blockIdx.x * 32, r0 = blockIdx.y * 32;
    int x = threadIdx.x & 31, y = (threadIdx.x >> 5) * 4;
#pragma unroll
    for (int i = 0; i < 4; ++i)
        tile[y + i][x] = in[(size_t)(r0 + y + i) * Cc + c0 + x];
    __syncthreads();
#pragma unroll
    for (int i = 0; i < 4; ++i)
        out[(size_t)(c0 + y + i) * R + r0 + x] = __float2half_rn(tile[x][y + i]);
}

// V transpose per (s,kv): g_vt16[b][d][t] = half(g_v[(s*SEQ+t)][kv*HD+d])
__global__ __launch_bounds__(256) void k_vtrans()
{
    __shared__ float tile[32][33];
    int b = blockIdx.z, s = b >> 2, kv = b & 3;
    const float* in = g_v + (size_t)s * SEQ * KD + kv * HD;
    __half* out = g_vt16 + (size_t)b * HD * SEQ;
    int d0 = blockIdx.x * 32, t0 = blockIdx.y * 32;
    int x = threadIdx.x & 31, y = (threadIdx.x >> 5) * 4;
#pragma unroll
    for (int i = 0; i < 4; ++i)
        tile[y + i][x] = in[(size_t)(t0 + y + i) * KD + d0 + x];
    __syncthreads();
#pragma unroll
    for (int i = 0; i < 4; ++i)
        out[(size_t)(d0 + y + i) * SEQ + t0 + x] = __float2half_rn(tile[x][y + i]);
}

// ---------------------------------------------------------------------------
// RMSNorm + RoPE; q scaled by SCALING; outputs fp16.
// ---------------------------------------------------------------------------
__device__ __forceinline__ void rmsrope_body(const float* __restrict__ x,
                                             __half* __restrict__ y,
                                             const float* __restrict__ w,
                                             const float* __restrict__ cosp,
                                             const float* __restrict__ sinp,
                                             int nh, float post_scale)
{
    int tok = blockIdx.x, h = blockIdx.y;
    const float* p = x + ((size_t)tok * nh + h) * HD;
    __half* o = y + ((size_t)tok * nh + h) * HD;
    int d = threadIdx.x;
    float v = p[d];
    float ssq = v * v;
#pragma unroll
    for (int off = 16; off > 0; off >>= 1) ssq += __shfl_xor_sync(0xffffffffu, ssq, off);
    __shared__ float ws[8];
    if ((d & 31) == 0) ws[d >> 5] = ssq;
    __syncthreads();
    float tot = 0.f;
#pragma unroll
    for (int i = 0; i < 8; i++) tot += ws[i];
    float r = rsqrtf(tot * (1.0f / HD) + EPS);
    float nv = v * r * (1.0f + w[d]);
    __shared__ float sn[HD];
    sn[d] = nv;
    __syncthreads();
    float rot = (d < HD / 2) ? -sn[d + HD / 2] : sn[d - HD / 2];
    float res = (nv * cosp[(size_t)tok * HD + d] + rot * sinp[(size_t)tok * HD + d]) * post_scale;
    o[d] = __float2half_rn(res);
}
__global__ __launch_bounds__(256) void k_rope_q(const float* w, const float* c, const float* s)
{ rmsrope_body(g_q, g_q16, w, c, s, NH, SCALING); }
__global__ __launch_bounds__(256) void k_rope_k(const float* w, const float* c, const float* s)
{ rmsrope_body(g_k, g_k16, w, c, s, NKV, 1.0f); }

// ---------------------------------------------------------------------------
// Row softmax: masks by column index (col>tok_in_seq -> -inf), fp16 P out.
// blockIdx.x = h*L_TOT + global_token; token within its seq = gtok % SEQ.
// ---------------------------------------------------------------------------
__global__ __launch_bounds__(256) void k_softmax()
{
    const float* row = g_scores + (size_t)blockIdx.x * SEQ;
    __half* prow = g_p16 + (size_t)blockIdx.x * SEQ;
    const int tok = (blockIdx.x % L_TOT) % SEQ;
    int d = threadIdx.x;
    int c0 = d * 4;
    float4 v = *(const float4*)(row + c0);
    v.x = (c0     > tok) ? -INFINITY : v.x;
    v.y = (c0 + 1 > tok) ? -INFINITY : v.y;
    v.z = (c0 + 2 > tok) ? -INFINITY : v.z;
    v.w = (c0 + 3 > tok) ? -INFINITY : v.w;

    float m = fmaxf(fmaxf(v.x, v.y), fmaxf(v.z, v.w));
#pragma unroll
    for (int o = 16; o > 0; o >>= 1) m = fmaxf(m, __shfl_xor_sync(0xffffffffu, m, o));
    __shared__ float wm[8];
    if ((d & 31) == 0) wm[d >> 5] = m;
    __syncthreads();
    float gm = wm[0];
#pragma unroll
    for (int i = 1; i < 8; i++) gm = fmaxf(gm, wm[i]);
    v.x = __expf(v.x - gm); v.y = __expf(v.y - gm);
    v.z = __expf(v.z - gm); v.w = __expf(v.w - gm);
    float ssum = v.x + v.y + v.z + v.w;
#pragma unroll
    for (int o = 16; o > 0; o >>= 1) ssum += __shfl_xor_sync(0xffffffffu, ssum, o);
    __shared__ float wsum[8];
    if ((d & 31) == 0) wsum[d >> 5] = ssum;
    __syncthreads();
    float tot = 0.f;
#pragma unroll
    for (int i = 0; i < 8; i++) tot += wsum[i];
    float inv = 1.0f / tot;
    *(__half2*)(prow + c0)     = __floats2half2_rn(v.x * inv, v.y * inv);
    *(__half2*)(prow + c0 + 2) = __floats2half2_rn(v.z * inv, v.w * inv);
}

// ---------------------------------------------------------------------------
// kernel_launch
// inputs: hidden_states, cos, sin, Wq, Wk, Wv, Wo, q_norm_w, k_norm_w, cu_seqlens
// ---------------------------------------------------------------------------
extern "C" void kernel_launch(void* const* d_in, const int* in_sizes, int n_in,
                              void* d_out, int out_size)
{
    const float* hs   = (const float*)d_in[0];
    const float* cosp = (const float*)d_in[1];
    const float* sinp = (const float*)d_in[2];
    const float* Wq   = (const float*)d_in[3];
    const float* Wk   = (const float*)d_in[4];
    const float* Wv   = (const float*)d_in[5];
    const float* Wo   = (const float*)d_in[6];
    const float* qw   = (const float*)d_in[7];
    const float* kw   = (const float*)d_in[8];
    float* out = (float*)d_out;

    cudaFuncSetAttribute(k_gemm16, cudaFuncAttributeMaxDynamicSharedMemorySize, SMEM_DYN);

    __half *p_hs16, *p_WqT16, *p_WkT16, *p_WvT16, *p_WoT16, *p_attn16;
    float  *p_q, *p_k, *p_v;
    cudaGetSymbolAddress((void**)&p_hs16,   g_hs16);
    cudaGetSymbolAddress((void**)&p_WqT16,  g_WqT16);
    cudaGetSymbolAddress((void**)&p_WkT16,  g_WkT16);
    cudaGetSymbolAddress((void**)&p_WvT16,  g_WvT16);
    cudaGetSymbolAddress((void**)&p_WoT16,  g_WoT16);
    cudaGetSymbolAddress((void**)&p_attn16, g_attn16);
    cudaGetSymbolAddress((void**)&p_q, g_q);
    cudaGetSymbolAddress((void**)&p_k, g_k);
    cudaGetSymbolAddress((void**)&p_v, g_v);

    dim3 thr(256);

    // 1) convert hidden states; transpose+convert weights
    k_cvt_hs<<<(L_TOT * HID) / 1024, thr>>>(hs);
    k_transpose_h<<<dim3(QD / 32, HID / 32), thr>>>(Wq, p_WqT16, HID, QD);
    k_transpose_h<<<dim3(KD / 32, HID / 32), thr>>>(Wk, p_WkT16, HID, KD);
    k_transpose_h<<<dim3(KD / 32, HID / 32), thr>>>(Wv, p_WvT16, HID, KD);
    k_transpose_h<<<dim3(HID / 32, QD / 32), thr>>>(Wo, p_WoT16, QD, HID);

    // 2) projections
    k_gemm16<<<dim3(QD / BN, L_TOT / BM), thr, SMEM_DYN>>>(p_hs16, p_WqT16, p_q, HID, HID, QD, HID, 0, 0);
    k_gemm16<<<dim3(KD / BN, L_TOT / BM), thr, SMEM_DYN>>>(p_hs16, p_WkT16, p_k, HID, HID, KD, HID, 0, 0);
    k_gemm16<<<dim3(KD / BN, L_TOT / BM), thr, SMEM_DYN>>>(p_hs16, p_WvT16, p_v, HID, HID, KD, HID, 0, 0);

    // 3) norm+rope; V transpose
    k_rope_q<<<dim3(L_TOT, NH),  thr>>>(qw, cosp, sinp);
    k_rope_k<<<dim3(L_TOT, NKV), thr>>>(kw, cosp, sinp);
    k_vtrans<<<dim3(HD / 32, SEQ / 32, NSEQ * NKV), thr>>>();

    // 4) scores (mask in epi; masked tiles skipped), softmax (index mask), PV (clamped)
    k_gemm16<<<dim3(SEQ / BN, SEQ / BM, NH * NSEQ), thr, SMEM_DYN>>>(
        nullptr, nullptr, nullptr, 0, 0, 0, HD, 1, 1);
    k_softmax<<<NH * L_TOT, thr>>>();
    k_gemm16<<<dim3(HD / BN, SEQ / BM, NH * NSEQ), thr, SMEM_DYN>>>(
        nullptr, nullptr, nullptr, 0, 0, 0, SEQ, 2, 2);

    // 5) output projection
    k_gemm16<<<dim3(HID / BN, L_TOT / BM), thr, SMEM_DYN>>>(p_attn16, p_WoT16, out, QD, QD, HID, QD, 0, 0);
}

// round 8
// speedup vs baseline: 5.4125x; 1.0392x over previous
#include <cuda_runtime.h>
#include <cuda_fp16.h>
#include <math.h>
#include <stdint.h>

// ---------------------------------------------------------------------------
// Problem constants
// ---------------------------------------------------------------------------
#define L_TOT   4096
#define HID     2560
#define NH      8
#define NKV     4
#define HD      256
#define QD      (NH*HD)    // 2048
#define KD      (NKV*HD)   // 1024
#define SEQ     1024
#define NSEQ    4
#define SCALING 0.0625f
#define EPS     1e-6f

// ---------------------------------------------------------------------------
// Scratch (__device__ globals)
// ---------------------------------------------------------------------------
__device__ __half g_hs16 [(size_t)L_TOT * HID];
__device__ __half g_WqT16[(size_t)QD * HID];
__device__ __half g_WkT16[(size_t)KD * HID];
__device__ __half g_WvT16[(size_t)KD * HID];
__device__ __half g_WoT16[(size_t)HID * QD];
__device__ float  g_q    [(size_t)L_TOT * QD];
__device__ float  g_k    [(size_t)L_TOT * KD];
__device__ float  g_v    [(size_t)L_TOT * KD];
__device__ __half g_q16  [(size_t)L_TOT * QD];
__device__ __half g_k16  [(size_t)L_TOT * KD];
__device__ __half g_vt16 [(size_t)NSEQ * NKV * HD * SEQ]; // [d][t]
__device__ float  g_scores[(size_t)NH * L_TOT * SEQ];
__device__ __half g_p16  [(size_t)NH * L_TOT * SEQ];
__device__ __half g_attn16[(size_t)L_TOT * QD];

// ---------------------------------------------------------------------------
// Helpers
// ---------------------------------------------------------------------------
__device__ __forceinline__ uint32_t smem_u32(const void* p) {
    uint32_t a;
    asm("{ .reg .u64 t; cvta.to.shared.u64 t, %1; cvt.u32.u64 %0, t; }"
        : "=r"(a) : "l"(p));
    return a;
}
__device__ __forceinline__ void cp_async16(uint32_t dst, const void* src) {
    asm volatile("cp.async.ca.shared.global [%0], [%1], 16;" :: "r"(dst), "l"(src));
}
#define CP_COMMIT()  asm volatile("cp.async.commit_group;" ::: "memory")
#define CP_WAIT(n)   asm volatile("cp.async.wait_group %0;" :: "n"(n) : "memory")

__device__ __forceinline__ void ldsm_x4(uint32_t* d, uint32_t addr) {
    asm volatile("ldmatrix.sync.aligned.m8n8.x4.shared.b16 {%0,%1,%2,%3}, [%4];"
                 : "=r"(d[0]), "=r"(d[1]), "=r"(d[2]), "=r"(d[3]) : "r"(addr));
}

// mma.sync m16n8k16 fp16 -> fp32
__device__ __forceinline__ void mma_f16(float* c, const uint32_t* a, const uint32_t* b) {
    asm volatile(
        "mma.sync.aligned.m16n8k16.row.col.f32.f16.f16.f32 "
        "{%0,%1,%2,%3}, {%4,%5,%6,%7}, {%8,%9}, {%0,%1,%2,%3};"
        : "+f"(c[0]), "+f"(c[1]), "+f"(c[2]), "+f"(c[3])
        : "r"(a[0]), "r"(a[1]), "r"(a[2]), "r"(a[3]), "r"(b[0]), "r"(b[1]));
}

// ---------------------------------------------------------------------------
// fp16 mma.sync GEMM: C(MxN) = A(MxK) * B(NxK)^T
// CTA 128x128, BK=64 halves, 3-stage cp.async, single sync per chunk,
// ldmatrix fragments. 256 thr (8 warps 2x4), warp tile 64x32.
// mode: 0=plain, 1=scores, 2=pv.  epi: 0=f32, 1=mask+f32, 2=half
// ---------------------------------------------------------------------------
#define BM 128
#define BN 128
#define BK 64
#define SKP 72                      // smem row stride in halves (144 B)
#define STG_H (BM * SKP)            // halves per A (or B) stage = 9216
#define SMEM_DYN (6 * STG_H * 2)    // 3 stages x (A+B) = 110592 B

__global__ __launch_bounds__(256, 2) void k_gemm16(
    const __half* __restrict__ A, const __half* __restrict__ B, void* __restrict__ Cv,
    int lda, int ldb, int ldc, int K, int mode, int epi)
{
    const int t    = threadIdx.x;
    const int lane = t & 31;
    const int wid  = t >> 5;
    const int grp  = lane >> 2;
    const int qid  = lane & 3;
    const int wm   = (wid >> 2) * 64;
    const int wn   = (wid & 3) * 32;
    const int m0   = blockIdx.y * BM;
    const int n0   = blockIdx.x * BN;

    float* Cf = (float*)Cv;
    __half* Ch = (__half*)Cv;

    if (mode == 1) {
        int h = blockIdx.z >> 2, s = blockIdx.z & 3;
        A  = g_q16 + (size_t)s * SEQ * QD + h * HD;                  lda = QD;
        B  = g_k16 + (size_t)s * SEQ * KD + (h >> 1) * HD;           ldb = KD;
        Cf = g_scores + ((size_t)h * L_TOT + (size_t)s * SEQ) * SEQ; ldc = SEQ;
    } else if (mode == 2) {
        int h = blockIdx.z >> 2, s = blockIdx.z & 3;
        A  = g_p16 + ((size_t)h * L_TOT + (size_t)s * SEQ) * SEQ;    lda = SEQ;
        B  = g_vt16 + ((size_t)(s * NKV + (h >> 1))) * HD * SEQ;     ldb = SEQ;
        Ch = g_attn16 + (size_t)s * SEQ * QD + h * HD;               ldc = QD;
    }

    // fully above causal diagonal: softmax masks by index -> nothing to do
    if (epi == 1 && n0 > m0 + (BM - 1)) return;

    extern __shared__ __half sm[];
    const uint32_t base = smem_u32(sm);

    float acc[4][4][4];
#pragma unroll
    for (int mi = 0; mi < 4; ++mi)
#pragma unroll
        for (int ni = 0; ni < 4; ++ni)
#pragma unroll
            for (int q = 0; q < 4; ++q) acc[mi][ni][q] = 0.f;

    int nc = K >> 6;
    if (mode == 2) {                       // causal clamp: P==0 beyond row band
        int lim = (m0 + BM) >> 6;
        if (lim < nc) nc = lim;
    }

    // staging coords: 1024 slots = 128 rows x 8 segs (A), same for B
    const int srow = t >> 3, sseg = t & 7;

    auto stage = [&](int c, int s) {
        const int k0 = c << 6;
        const uint32_t offA = base + (uint32_t)(s * STG_H) * 2;
        const uint32_t offB = base + (uint32_t)((3 + s) * STG_H) * 2;
#pragma unroll
        for (int l = 0; l < 4; ++l) {
            int row = srow + l * 32;
            cp_async16(offA + (uint32_t)(row * SKP + sseg * 8) * 2,
                       A + (size_t)(m0 + row) * lda + k0 + sseg * 8);
        }
#pragma unroll
        for (int l = 0; l < 4; ++l) {
            int row = srow + l * 32;
            cp_async16(offB + (uint32_t)(row * SKP + sseg * 8) * 2,
                       B + (size_t)(n0 + row) * ldb + k0 + sseg * 8);
        }
        CP_COMMIT();
    };

    // per-lane ldmatrix byte offsets (within a stage)
    const uint32_t aRow = wm + (lane & 15);
    const uint32_t aCol = (lane & 16) ? 8u : 0u;
    const uint32_t aOffBase = (aRow * SKP + aCol) * 2;
    const uint32_t bRow = wn + (lane & 7) + ((lane & 16) ? 8u : 0u);
    const uint32_t bCol = (lane & 8) ? 8u : 0u;
    const uint32_t bOffBase = (bRow * SKP + bCol) * 2;

    stage(0, 0);
    if (nc > 1) stage(1, 1);

    for (int c = 0; c < nc; ++c) {
        const int s = c % 3;
        if (c + 1 < nc) { CP_WAIT(1); } else { CP_WAIT(0); }
        __syncthreads();
        if (c + 2 < nc) stage(c + 2, (c + 2) % 3);

        const uint32_t uA = base + (uint32_t)(s * STG_H) * 2 + aOffBase;
        const uint32_t uB = base + (uint32_t)((3 + s) * STG_H) * 2 + bOffBase;

#pragma unroll
        for (int ks = 0; ks < 4; ++ks) {
            uint32_t au[4][4], bu[2][4];
#pragma unroll
            for (int mi = 0; mi < 4; ++mi)
                ldsm_x4(au[mi], uA + (uint32_t)(mi * 16 * SKP + ks * 16) * 2);
#pragma unroll
            for (int p = 0; p < 2; ++p)
                ldsm_x4(bu[p], uB + (uint32_t)(p * 16 * SKP + ks * 16) * 2);
#pragma unroll
            for (int mi = 0; mi < 4; ++mi)
#pragma unroll
                for (int ni = 0; ni < 4; ++ni)
                    mma_f16(acc[mi][ni], au[mi], &bu[ni >> 1][(ni & 1) * 2]);
        }
        // NOTE: no trailing sync — next overwrite of this stage happens only
        // after the sync at iteration c+1 (see reorder proof in commit msg).
    }

    // epilogue
#pragma unroll
    for (int mi = 0; mi < 4; ++mi) {
#pragma unroll
        for (int ni = 0; ni < 4; ++ni) {
            int gm = m0 + wm + mi * 16 + grp;
            int gn = n0 + wn + ni * 8 + 2 * qid;
            float v0 = acc[mi][ni][0], v1 = acc[mi][ni][1];
            float v2 = acc[mi][ni][2], v3 = acc[mi][ni][3];
            if (epi == 1) {
                v0 = (gn     > gm)     ? -INFINITY : v0;
                v1 = (gn + 1 > gm)     ? -INFINITY : v1;
                v2 = (gn     > gm + 8) ? -INFINITY : v2;
                v3 = (gn + 1 > gm + 8) ? -INFINITY : v3;
                *(float2*)(Cf + (size_t)gm * ldc + gn)       = make_float2(v0, v1);
                *(float2*)(Cf + (size_t)(gm + 8) * ldc + gn) = make_float2(v2, v3);
            } else if (epi == 2) {
                *(__half2*)(Ch + (size_t)gm * ldc + gn)       = __floats2half2_rn(v0, v1);
                *(__half2*)(Ch + (size_t)(gm + 8) * ldc + gn) = __floats2half2_rn(v2, v3);
            } else {
                *(float2*)(Cf + (size_t)gm * ldc + gn)       = make_float2(v0, v1);
                *(float2*)(Cf + (size_t)(gm + 8) * ldc + gn) = make_float2(v2, v3);
            }
        }
    }
}

// ---------------------------------------------------------------------------
// hidden_states fp32 -> fp16
// ---------------------------------------------------------------------------
__global__ __launch_bounds__(256) void k_cvt_hs(const float* __restrict__ in)
{
    size_t i = ((size_t)blockIdx.x * 256 + threadIdx.x) * 4;
    float4 v = *(const float4*)(in + i);
    *(__half2*)(g_hs16 + i)     = __floats2half2_rn(v.x, v.y);
    *(__half2*)(g_hs16 + i + 2) = __floats2half2_rn(v.z, v.w);
}

// ---------------------------------------------------------------------------
// Transpose + cvt: out(half)[n][k] = in(f32)[k][n]; in is R x Cc
// ---------------------------------------------------------------------------
__global__ __launch_bounds__(256) void k_transpose_h(
    const float* __restrict__ in, __half* __restrict__ out, int R, int Cc)
{
    __shared__ float tile[32][33];
    int c0 = blockIdx.x * 32, r0 = blockIdx.y * 32;
    int x = threadIdx.x & 31, y = (threadIdx.x >> 5) * 4;
#pragma unroll
    for (int i = 0; i < 4; ++i)
        tile[y + i][x] = in[(size_t)(r0 + y + i) * Cc + c0 + x];
    __syncthreads();
#pragma unroll
    for (int i = 0; i < 4; ++i)
        out[(size_t)(c0 + y + i) * R + r0 + x] = __float2half_rn(tile[x][y + i]);
}

// V transpose per (s,kv): g_vt16[b][d][t] = half(g_v[(s*SEQ+t)][kv*HD+d])
__global__ __launch_bounds__(256) void k_vtrans()
{
    __shared__ float tile[32][33];
    int b = blockIdx.z, s = b >> 2, kv = b & 3;
    const float* in = g_v + (size_t)s * SEQ * KD + kv * HD;
    __half* out = g_vt16 + (size_t)b * HD * SEQ;
    int d0 = blockIdx.x * 32, t0 = blockIdx.y * 32;
    int x = threadIdx.x & 31, y = (threadIdx.x >> 5) * 4;
#pragma unroll
    for (int i = 0; i < 4; ++i)
        tile[y + i][x] = in[(size_t)(t0 + y + i) * KD + d0 + x];
    __syncthreads();
#pragma unroll
    for (int i = 0; i < 4; ++i)
        out[(size_t)(d0 + y + i) * SEQ + t0 + x] = __float2half_rn(tile[x][y + i]);
}

// ---------------------------------------------------------------------------
// RMSNorm + RoPE; q scaled by SCALING; outputs fp16.
// ---------------------------------------------------------------------------
__device__ __forceinline__ void rmsrope_body(const float* __restrict__ x,
                                             __half* __restrict__ y,
                                             const float* __restrict__ w,
                                             const float* __restrict__ cosp,
                                             const float* __restrict__ sinp,
                                             int nh, float post_scale)
{
    int tok = blockIdx.x, h = blockIdx.y;
    const float* p = x + ((size_t)tok * nh + h) * HD;
    __half* o = y + ((size_t)tok * nh + h) * HD;
    int d = threadIdx.x;
    float v = p[d];
    float ssq = v * v;
#pragma unroll
    for (int off = 16; off > 0; off >>= 1) ssq += __shfl_xor_sync(0xffffffffu, ssq, off);
    __shared__ float ws[8];
    if ((d & 31) == 0) ws[d >> 5] = ssq;
    __syncthreads();
    float tot = 0.f;
#pragma unroll
    for (int i = 0; i < 8; i++) tot += ws[i];
    float r = rsqrtf(tot * (1.0f / HD) + EPS);
    float nv = v * r * (1.0f + w[d]);
    __shared__ float sn[HD];
    sn[d] = nv;
    __syncthreads();
    float rot = (d < HD / 2) ? -sn[d + HD / 2] : sn[d - HD / 2];
    float res = (nv * cosp[(size_t)tok * HD + d] + rot * sinp[(size_t)tok * HD + d]) * post_scale;
    o[d] = __float2half_rn(res);
}
__global__ __launch_bounds__(256) void k_rope_q(const float* w, const float* c, const float* s)
{ rmsrope_body(g_q, g_q16, w, c, s, NH, SCALING); }
__global__ __launch_bounds__(256) void k_rope_k(const float* w, const float* c, const float* s)
{ rmsrope_body(g_k, g_k16, w, c, s, NKV, 1.0f); }

// ---------------------------------------------------------------------------
// Row softmax: masks by column index (col>tok_in_seq -> -inf), fp16 P out.
// ---------------------------------------------------------------------------
__global__ __launch_bounds__(256) void k_softmax()
{
    const float* row = g_scores + (size_t)blockIdx.x * SEQ;
    __half* prow = g_p16 + (size_t)blockIdx.x * SEQ;
    const int tok = (blockIdx.x % L_TOT) % SEQ;
    int d = threadIdx.x;
    int c0 = d * 4;
    float4 v = *(const float4*)(row + c0);
    v.x = (c0     > tok) ? -INFINITY : v.x;
    v.y = (c0 + 1 > tok) ? -INFINITY : v.y;
    v.z = (c0 + 2 > tok) ? -INFINITY : v.z;
    v.w = (c0 + 3 > tok) ? -INFINITY : v.w;

    float m = fmaxf(fmaxf(v.x, v.y), fmaxf(v.z, v.w));
#pragma unroll
    for (int o = 16; o > 0; o >>= 1) m = fmaxf(m, __shfl_xor_sync(0xffffffffu, m, o));
    __shared__ float wm[8];
    if ((d & 31) == 0) wm[d >> 5] = m;
    __syncthreads();
    float gm = wm[0];
#pragma unroll
    for (int i = 1; i < 8; i++) gm = fmaxf(gm, wm[i]);
    v.x = __expf(v.x - gm); v.y = __expf(v.y - gm);
    v.z = __expf(v.z - gm); v.w = __expf(v.w - gm);
    float ssum = v.x + v.y + v.z + v.w;
#pragma unroll
    for (int o = 16; o > 0; o >>= 1) ssum += __shfl_xor_sync(0xffffffffu, ssum, o);
    __shared__ float wsum[8];
    if ((d & 31) == 0) wsum[d >> 5] = ssum;
    __syncthreads();
    float tot = 0.f;
#pragma unroll
    for (int i = 0; i < 8; i++) tot += wsum[i];
    float inv = 1.0f / tot;
    *(__half2*)(prow + c0)     = __floats2half2_rn(v.x * inv, v.y * inv);
    *(__half2*)(prow + c0 + 2) = __floats2half2_rn(v.z * inv, v.w * inv);
}

// ---------------------------------------------------------------------------
// kernel_launch
// ---------------------------------------------------------------------------
extern "C" void kernel_launch(void* const* d_in, const int* in_sizes, int n_in,
                              void* d_out, int out_size)
{
    const float* hs   = (const float*)d_in[0];
    const float* cosp = (const float*)d_in[1];
    const float* sinp = (const float*)d_in[2];
    const float* Wq   = (const float*)d_in[3];
    const float* Wk   = (const float*)d_in[4];
    const float* Wv   = (const float*)d_in[5];
    const float* Wo   = (const float*)d_in[6];
    const float* qw   = (const float*)d_in[7];
    const float* kw   = (const float*)d_in[8];
    float* out = (float*)d_out;

    cudaFuncSetAttribute(k_gemm16, cudaFuncAttributeMaxDynamicSharedMemorySize, SMEM_DYN);

    __half *p_hs16, *p_WqT16, *p_WkT16, *p_WvT16, *p_WoT16, *p_attn16;
    float  *p_q, *p_k, *p_v;
    cudaGetSymbolAddress((void**)&p_hs16,   g_hs16);
    cudaGetSymbolAddress((void**)&p_WqT16,  g_WqT16);
    cudaGetSymbolAddress((void**)&p_WkT16,  g_WkT16);
    cudaGetSymbolAddress((void**)&p_WvT16,  g_WvT16);
    cudaGetSymbolAddress((void**)&p_WoT16,  g_WoT16);
    cudaGetSymbolAddress((void**)&p_attn16, g_attn16);
    cudaGetSymbolAddress((void**)&p_q, g_q);
    cudaGetSymbolAddress((void**)&p_k, g_k);
    cudaGetSymbolAddress((void**)&p_v, g_v);

    dim3 thr(256);

    // 1) convert hidden states; transpose+convert weights
    k_cvt_hs<<<(L_TOT * HID) / 1024, thr>>>(hs);
    k_transpose_h<<<dim3(QD / 32, HID / 32), thr>>>(Wq, p_WqT16, HID, QD);
    k_transpose_h<<<dim3(KD / 32, HID / 32), thr>>>(Wk, p_WkT16, HID, KD);
    k_transpose_h<<<dim3(KD / 32, HID / 32), thr>>>(Wv, p_WvT16, HID, KD);
    k_transpose_h<<<dim3(HID / 32, QD / 32), thr>>>(Wo, p_WoT16, QD, HID);

    // 2) projections  (K=2560 = 40 chunks of 64)
    k_gemm16<<<dim3(QD / BN, L_TOT / BM), thr, SMEM_DYN>>>(p_hs16, p_WqT16, p_q, HID, HID, QD, HID, 0, 0);
    k_gemm16<<<dim3(KD / BN, L_TOT / BM), thr, SMEM_DYN>>>(p_hs16, p_WkT16, p_k, HID, HID, KD, HID, 0, 0);
    k_gemm16<<<dim3(KD / BN, L_TOT / BM), thr, SMEM_DYN>>>(p_hs16, p_WvT16, p_v, HID, HID, KD, HID, 0, 0);

    // 3) norm+rope; V transpose
    k_rope_q<<<dim3(L_TOT, NH),  thr>>>(qw, cosp, sinp);
    k_rope_k<<<dim3(L_TOT, NKV), thr>>>(kw, cosp, sinp);
    k_vtrans<<<dim3(HD / 32, SEQ / 32, NSEQ * NKV), thr>>>();

    // 4) scores (mask in epi; masked tiles skipped), softmax, PV (clamped)
    k_gemm16<<<dim3(SEQ / BN, SEQ / BM, NH * NSEQ), thr, SMEM_DYN>>>(
        nullptr, nullptr, nullptr, 0, 0, 0, HD, 1, 1);
    k_softmax<<<NH * L_TOT, thr>>>();
    k_gemm16<<<dim3(HD / BN, SEQ / BM, NH * NSEQ), thr, SMEM_DYN>>>(
        nullptr, nullptr, nullptr, 0, 0, 0, SEQ, 2, 2);

    // 5) output projection
    k_gemm16<<<dim3(HID / BN, L_TOT / BM), thr, SMEM_DYN>>>(p_attn16, p_WoT16, out, QD, QD, HID, QD, 0, 0);
}

// round 9
// speedup vs baseline: 6.1806x; 1.1419x over previous
#include <cuda_runtime.h>
#include <cuda_fp16.h>
#include <math.h>
#include <stdint.h>

// ---------------------------------------------------------------------------
// Problem constants
// ---------------------------------------------------------------------------
#define L_TOT   4096
#define HID     2560
#define NH      8
#define NKV     4
#define HD      256
#define QD      (NH*HD)    // 2048
#define KD      (NKV*HD)   // 1024
#define SEQ     1024
#define NSEQ    4
#define SCALING 0.0625f
#define EPS     1e-6f

// ---------------------------------------------------------------------------
// Scratch (__device__ globals)
// ---------------------------------------------------------------------------
__device__ __half g_hs16 [(size_t)L_TOT * HID];
__device__ __half g_WqT16[(size_t)QD * HID];
__device__ __half g_WkT16[(size_t)KD * HID];
__device__ __half g_WvT16[(size_t)KD * HID];
__device__ __half g_WoT16[(size_t)HID * QD];
__device__ float  g_q    [(size_t)L_TOT * QD];
__device__ float  g_k    [(size_t)L_TOT * KD];
__device__ float  g_v    [(size_t)L_TOT * KD];
__device__ __half g_q16  [(size_t)L_TOT * QD];
__device__ __half g_k16  [(size_t)L_TOT * KD];
__device__ __half g_vt16 [(size_t)NSEQ * NKV * HD * SEQ]; // [d][t]
__device__ float  g_scores[(size_t)NH * L_TOT * SEQ];
__device__ __half g_p16  [(size_t)NH * L_TOT * SEQ];
__device__ __half g_attn16[(size_t)L_TOT * QD];

// ---------------------------------------------------------------------------
// Helpers
// ---------------------------------------------------------------------------
__device__ __forceinline__ uint32_t smem_u32(const void* p) {
    uint32_t a;
    asm("{ .reg .u64 t; cvta.to.shared.u64 t, %1; cvt.u32.u64 %0, t; }"
        : "=r"(a) : "l"(p));
    return a;
}
__device__ __forceinline__ void cp_async16(uint32_t dst, const void* src) {
    asm volatile("cp.async.ca.shared.global [%0], [%1], 16;" :: "r"(dst), "l"(src));
}
#define CP_COMMIT()  asm volatile("cp.async.commit_group;" ::: "memory")
#define CP_WAIT(n)   asm volatile("cp.async.wait_group %0;" :: "n"(n) : "memory")

__device__ __forceinline__ void ldsm_x4(uint32_t* d, uint32_t addr) {
    asm volatile("ldmatrix.sync.aligned.m8n8.x4.shared.b16 {%0,%1,%2,%3}, [%4];"
                 : "=r"(d[0]), "=r"(d[1]), "=r"(d[2]), "=r"(d[3]) : "r"(addr));
}

// mma.sync m16n8k16 fp16 -> fp32
__device__ __forceinline__ void mma_f16(float* c, const uint32_t* a, const uint32_t* b) {
    asm volatile(
        "mma.sync.aligned.m16n8k16.row.col.f32.f16.f16.f32 "
        "{%0,%1,%2,%3}, {%4,%5,%6,%7}, {%8,%9}, {%0,%1,%2,%3};"
        : "+f"(c[0]), "+f"(c[1]), "+f"(c[2]), "+f"(c[3])
        : "r"(a[0]), "r"(a[1]), "r"(a[2]), "r"(a[3]), "r"(b[0]), "r"(b[1]));
}

// ---------------------------------------------------------------------------
// fp16 mma.sync GEMM: C(MxN) = A(MxK) * B(NxK)^T
// CTA 128x128, BK=64 halves, 3-stage cp.async, single sync per chunk.
// mode: 0=plain, 1=scores, 2=pv, 3=fused QKV.  epi: 0=f32, 1=mask, 2=half
// ---------------------------------------------------------------------------
#define BM 128
#define BN 128
#define BK 64
#define SKP 72
#define STG_H (BM * SKP)            // 9216 halves
#define SMEM_DYN (6 * STG_H * 2)    // 110592 B

__global__ __launch_bounds__(256, 2) void k_gemm16(
    const __half* __restrict__ A, const __half* __restrict__ B, void* __restrict__ Cv,
    int lda, int ldb, int ldc, int K, int mode, int epi)
{
    const int t    = threadIdx.x;
    const int lane = t & 31;
    const int wid  = t >> 5;
    const int grp  = lane >> 2;
    const int qid  = lane & 3;
    const int wm   = (wid >> 2) * 64;
    const int wn   = (wid & 3) * 32;
    int m0 = blockIdx.y * BM;
    int n0 = blockIdx.x * BN;

    float* Cf = (float*)Cv;
    __half* Ch = (__half*)Cv;

    if (mode == 1) {
        int h = blockIdx.z >> 2, s = blockIdx.z & 3;
        A  = g_q16 + (size_t)s * SEQ * QD + h * HD;                  lda = QD;
        B  = g_k16 + (size_t)s * SEQ * KD + (h >> 1) * HD;           ldb = KD;
        Cf = g_scores + ((size_t)h * L_TOT + (size_t)s * SEQ) * SEQ; ldc = SEQ;
    } else if (mode == 2) {
        int h = blockIdx.z >> 2, s = blockIdx.z & 3;
        m0 = (gridDim.y - 1 - blockIdx.y) * BM;        // longest CTAs first
        A  = g_p16 + ((size_t)h * L_TOT + (size_t)s * SEQ) * SEQ;    lda = SEQ;
        B  = g_vt16 + ((size_t)(s * NKV + (h >> 1))) * HD * SEQ;     ldb = SEQ;
        Ch = g_attn16 + (size_t)s * SEQ * QD + h * HD;               ldc = QD;
    } else if (mode == 3) {
        // fused QKV: x<16 -> Q tile, 16..23 -> K, 24..31 -> V
        int x = blockIdx.x;
        A = g_hs16; lda = HID; ldb = HID; K = HID;
        if (x < 16)      { B = g_WqT16; Cf = g_q; n0 = x * BN;        ldc = QD; }
        else if (x < 24) { B = g_WkT16; Cf = g_k; n0 = (x - 16) * BN; ldc = KD; }
        else             { B = g_WvT16; Cf = g_v; n0 = (x - 24) * BN; ldc = KD; }
    }

    // fully above causal diagonal: softmax masks by index -> nothing to do
    if (epi == 1 && n0 > m0 + (BM - 1)) return;

    extern __shared__ __half sm[];
    const uint32_t base = smem_u32(sm);

    float acc[4][4][4];
#pragma unroll
    for (int mi = 0; mi < 4; ++mi)
#pragma unroll
        for (int ni = 0; ni < 4; ++ni)
#pragma unroll
            for (int q = 0; q < 4; ++q) acc[mi][ni][q] = 0.f;

    int nc = K >> 6;
    if (mode == 2) {                       // causal clamp
        int lim = (m0 + BM) >> 6;
        if (lim < nc) nc = lim;
    }

    const int srow = t >> 3, sseg = t & 7;

    auto stage = [&](int c, int s) {
        const int k0 = c << 6;
        const uint32_t offA = base + (uint32_t)(s * STG_H) * 2;
        const uint32_t offB = base + (uint32_t)((3 + s) * STG_H) * 2;
#pragma unroll
        for (int l = 0; l < 4; ++l) {
            int row = srow + l * 32;
            cp_async16(offA + (uint32_t)(row * SKP + sseg * 8) * 2,
                       A + (size_t)(m0 + row) * lda + k0 + sseg * 8);
        }
#pragma unroll
        for (int l = 0; l < 4; ++l) {
            int row = srow + l * 32;
            cp_async16(offB + (uint32_t)(row * SKP + sseg * 8) * 2,
                       B + (size_t)(n0 + row) * ldb + k0 + sseg * 8);
        }
        CP_COMMIT();
    };

    const uint32_t aRow = wm + (lane & 15);
    const uint32_t aCol = (lane & 16) ? 8u : 0u;
    const uint32_t aOffBase = (aRow * SKP + aCol) * 2;
    const uint32_t bRow = wn + (lane & 7) + ((lane & 16) ? 8u : 0u);
    const uint32_t bCol = (lane & 8) ? 8u : 0u;
    const uint32_t bOffBase = (bRow * SKP + bCol) * 2;

    stage(0, 0);
    if (nc > 1) stage(1, 1);

    for (int c = 0; c < nc; ++c) {
        const int s = c % 3;
        if (c + 1 < nc) { CP_WAIT(1); } else { CP_WAIT(0); }
        __syncthreads();
        if (c + 2 < nc) stage(c + 2, (c + 2) % 3);

        const uint32_t uA = base + (uint32_t)(s * STG_H) * 2 + aOffBase;
        const uint32_t uB = base + (uint32_t)((3 + s) * STG_H) * 2 + bOffBase;

#pragma unroll
        for (int ks = 0; ks < 4; ++ks) {
            uint32_t au[4][4], bu[2][4];
#pragma unroll
            for (int mi = 0; mi < 4; ++mi)
                ldsm_x4(au[mi], uA + (uint32_t)(mi * 16 * SKP + ks * 16) * 2);
#pragma unroll
            for (int p = 0; p < 2; ++p)
                ldsm_x4(bu[p], uB + (uint32_t)(p * 16 * SKP + ks * 16) * 2);
#pragma unroll
            for (int mi = 0; mi < 4; ++mi)
#pragma unroll
                for (int ni = 0; ni < 4; ++ni)
                    mma_f16(acc[mi][ni], au[mi], &bu[ni >> 1][(ni & 1) * 2]);
        }
    }

    // epilogue
#pragma unroll
    for (int mi = 0; mi < 4; ++mi) {
#pragma unroll
        for (int ni = 0; ni < 4; ++ni) {
            int gm = m0 + wm + mi * 16 + grp;
            int gn = n0 + wn + ni * 8 + 2 * qid;
            float v0 = acc[mi][ni][0], v1 = acc[mi][ni][1];
            float v2 = acc[mi][ni][2], v3 = acc[mi][ni][3];
            if (epi == 1) {
                v0 = (gn     > gm)     ? -INFINITY : v0;
                v1 = (gn + 1 > gm)     ? -INFINITY : v1;
                v2 = (gn     > gm + 8) ? -INFINITY : v2;
                v3 = (gn + 1 > gm + 8) ? -INFINITY : v3;
                *(float2*)(Cf + (size_t)gm * ldc + gn)       = make_float2(v0, v1);
                *(float2*)(Cf + (size_t)(gm + 8) * ldc + gn) = make_float2(v2, v3);
            } else if (epi == 2) {
                *(__half2*)(Ch + (size_t)gm * ldc + gn)       = __floats2half2_rn(v0, v1);
                *(__half2*)(Ch + (size_t)(gm + 8) * ldc + gn) = __floats2half2_rn(v2, v3);
            } else {
                *(float2*)(Cf + (size_t)gm * ldc + gn)       = make_float2(v0, v1);
                *(float2*)(Cf + (size_t)(gm + 8) * ldc + gn) = make_float2(v2, v3);
            }
        }
    }
}

// ---------------------------------------------------------------------------
// hidden_states fp32 -> fp16
// ---------------------------------------------------------------------------
__global__ __launch_bounds__(256) void k_cvt_hs(const float* __restrict__ in)
{
    size_t i = ((size_t)blockIdx.x * 256 + threadIdx.x) * 4;
    float4 v = *(const float4*)(in + i);
    *(__half2*)(g_hs16 + i)     = __floats2half2_rn(v.x, v.y);
    *(__half2*)(g_hs16 + i + 2) = __floats2half2_rn(v.z, v.w);
}

// ---------------------------------------------------------------------------
// Transpose + cvt
// ---------------------------------------------------------------------------
__global__ __launch_bounds__(256) void k_transpose_h(
    const float* __restrict__ in, __half* __restrict__ out, int R, int Cc)
{
    __shared__ float tile[32][33];
    int c0 = blockIdx.x * 32, r0 = blockIdx.y * 32;
    int x = threadIdx.x & 31, y = (threadIdx.x >> 5) * 4;
#pragma unroll
    for (int i = 0; i < 4; ++i)
        tile[y + i][x] = in[(size_t)(r0 + y + i) * Cc + c0 + x];
    __syncthreads();
#pragma unroll
    for (int i = 0; i < 4; ++i)
        out[(size_t)(c0 + y + i) * R + r0 + x] = __float2half_rn(tile[x][y + i]);
}

__global__ __launch_bounds__(256) void k_vtrans()
{
    __shared__ float tile[32][33];
    int b = blockIdx.z, s = b >> 2, kv = b & 3;
    const float* in = g_v + (size_t)s * SEQ * KD + kv * HD;
    __half* out = g_vt16 + (size_t)b * HD * SEQ;
    int d0 = blockIdx.x * 32, t0 = blockIdx.y * 32;
    int x = threadIdx.x & 31, y = (threadIdx.x >> 5) * 4;
#pragma unroll
    for (int i = 0; i < 4; ++i)
        tile[y + i][x] = in[(size_t)(t0 + y + i) * KD + d0 + x];
    __syncthreads();
#pragma unroll
    for (int i = 0; i < 4; ++i)
        out[(size_t)(d0 + y + i) * SEQ + t0 + x] = __float2half_rn(tile[x][y + i]);
}

// ---------------------------------------------------------------------------
// Warp-per-head RMSNorm + RoPE. d = lane + 32*j layout (rot partner is j+-4,
// same lane -> no shared memory, warp shuffles only).
//   q: grid L_TOT blocks, 8 warps = 8 heads.
//   k: grid L_TOT/2 blocks, 8 warps = 2 tokens x 4 heads.
// ---------------------------------------------------------------------------
template<int NHEADS, int TPB>
__device__ __forceinline__ void rope_warp(const float* __restrict__ x,
                                          __half* __restrict__ y,
                                          const float* __restrict__ w,
                                          const float* __restrict__ cosp,
                                          const float* __restrict__ sinp,
                                          float post_scale)
{
    const int warp = threadIdx.x >> 5;
    const int lane = threadIdx.x & 31;
    const int warps_per_tok = NHEADS;
    const int toks_per_blk = (TPB / 32) / warps_per_tok;
    const int tok = blockIdx.x * toks_per_blk + warp / warps_per_tok;
    const int h   = warp % warps_per_tok;

    const float* p = x + ((size_t)tok * NHEADS + h) * HD;
    __half* o = y + ((size_t)tok * NHEADS + h) * HD;

    float v[8];
    float ssq = 0.f;
#pragma unroll
    for (int j = 0; j < 8; ++j) {
        v[j] = p[lane + 32 * j];
        ssq += v[j] * v[j];
    }
#pragma unroll
    for (int off = 16; off > 0; off >>= 1) ssq += __shfl_xor_sync(0xffffffffu, ssq, off);
    float r = rsqrtf(ssq * (1.0f / HD) + EPS);

    float nv[8];
#pragma unroll
    for (int j = 0; j < 8; ++j)
        nv[j] = v[j] * r * (1.0f + w[lane + 32 * j]);

#pragma unroll
    for (int j = 0; j < 8; ++j) {
        int d = lane + 32 * j;
        float rot = (j < 4) ? -nv[j + 4] : nv[j - 4];
        float res = (nv[j] * cosp[(size_t)tok * HD + d] + rot * sinp[(size_t)tok * HD + d]) * post_scale;
        o[d] = __float2half_rn(res);
    }
}
__global__ __launch_bounds__(256) void k_rope_q(const float* w, const float* c, const float* s)
{ rope_warp<NH, 256>(g_q, g_q16, w, c, s, SCALING); }
__global__ __launch_bounds__(256) void k_rope_k(const float* w, const float* c, const float* s)
{ rope_warp<NKV, 256>(g_k, g_k16, w, c, s, 1.0f); }

// ---------------------------------------------------------------------------
// Warp-per-row softmax over 1024 cols, index mask, fp16 P out.
// 8 rows per 256-thread block. Shuffle-only reductions.
// ---------------------------------------------------------------------------
__global__ __launch_bounds__(256) void k_softmax()
{
    const int r    = blockIdx.x * 8 + (threadIdx.x >> 5);
    const int lane = threadIdx.x & 31;
    const float* row = g_scores + (size_t)r * SEQ;
    __half* prow = g_p16 + (size_t)r * SEQ;
    const int tok = r & (SEQ - 1);   // (r % L_TOT) % SEQ == r & 1023

    float4 v[8];
    float m = -INFINITY;
#pragma unroll
    for (int i = 0; i < 8; ++i) {
        int c0 = i * 128 + lane * 4;
        v[i] = *(const float4*)(row + c0);
        v[i].x = (c0     > tok) ? -INFINITY : v[i].x;
        v[i].y = (c0 + 1 > tok) ? -INFINITY : v[i].y;
        v[i].z = (c0 + 2 > tok) ? -INFINITY : v[i].z;
        v[i].w = (c0 + 3 > tok) ? -INFINITY : v[i].w;
        m = fmaxf(m, fmaxf(fmaxf(v[i].x, v[i].y), fmaxf(v[i].z, v[i].w)));
    }
#pragma unroll
    for (int o = 16; o > 0; o >>= 1) m = fmaxf(m, __shfl_xor_sync(0xffffffffu, m, o));

    float ssum = 0.f;
#pragma unroll
    for (int i = 0; i < 8; ++i) {
        v[i].x = __expf(v[i].x - m); v[i].y = __expf(v[i].y - m);
        v[i].z = __expf(v[i].z - m); v[i].w = __expf(v[i].w - m);
        ssum += (v[i].x + v[i].y) + (v[i].z + v[i].w);
    }
#pragma unroll
    for (int o = 16; o > 0; o >>= 1) ssum += __shfl_xor_sync(0xffffffffu, ssum, o);
    float inv = 1.0f / ssum;

#pragma unroll
    for (int i = 0; i < 8; ++i) {
        int c0 = i * 128 + lane * 4;
        *(__half2*)(prow + c0)     = __floats2half2_rn(v[i].x * inv, v[i].y * inv);
        *(__half2*)(prow + c0 + 2) = __floats2half2_rn(v[i].z * inv, v[i].w * inv);
    }
}

// ---------------------------------------------------------------------------
// kernel_launch
// ---------------------------------------------------------------------------
extern "C" void kernel_launch(void* const* d_in, const int* in_sizes, int n_in,
                              void* d_out, int out_size)
{
    const float* hs   = (const float*)d_in[0];
    const float* cosp = (const float*)d_in[1];
    const float* sinp = (const float*)d_in[2];
    const float* Wq   = (const float*)d_in[3];
    const float* Wk   = (const float*)d_in[4];
    const float* Wv   = (const float*)d_in[5];
    const float* Wo   = (const float*)d_in[6];
    const float* qw   = (const float*)d_in[7];
    const float* kw   = (const float*)d_in[8];
    float* out = (float*)d_out;

    cudaFuncSetAttribute(k_gemm16, cudaFuncAttributeMaxDynamicSharedMemorySize, SMEM_DYN);

    __half *p_WqT16, *p_WkT16, *p_WvT16, *p_WoT16, *p_attn16;
    cudaGetSymbolAddress((void**)&p_WqT16,  g_WqT16);
    cudaGetSymbolAddress((void**)&p_WkT16,  g_WkT16);
    cudaGetSymbolAddress((void**)&p_WvT16,  g_WvT16);
    cudaGetSymbolAddress((void**)&p_WoT16,  g_WoT16);
    cudaGetSymbolAddress((void**)&p_attn16, g_attn16);

    dim3 thr(256);

    // 1) convert hidden states; transpose+convert weights
    k_cvt_hs<<<(L_TOT * HID) / 1024, thr>>>(hs);
    k_transpose_h<<<dim3(QD / 32, HID / 32), thr>>>(Wq, p_WqT16, HID, QD);
    k_transpose_h<<<dim3(KD / 32, HID / 32), thr>>>(Wk, p_WkT16, HID, KD);
    k_transpose_h<<<dim3(KD / 32, HID / 32), thr>>>(Wv, p_WvT16, HID, KD);
    k_transpose_h<<<dim3(HID / 32, QD / 32), thr>>>(Wo, p_WoT16, QD, HID);

    // 2) fused QKV projection: one launch, 1024 CTAs
    k_gemm16<<<dim3(32, L_TOT / BM), thr, SMEM_DYN>>>(
        nullptr, nullptr, nullptr, 0, 0, 0, HID, 3, 0);

    // 3) norm+rope (warp-per-head); V transpose
    k_rope_q<<<L_TOT, thr>>>(qw, cosp, sinp);
    k_rope_k<<<L_TOT / 2, thr>>>(kw, cosp, sinp);
    k_vtrans<<<dim3(HD / 32, SEQ / 32, NSEQ * NKV), thr>>>();

    // 4) scores (masked tiles skipped), softmax (warp-per-row), PV (clamped, reversed)
    k_gemm16<<<dim3(SEQ / BN, SEQ / BM, NH * NSEQ), thr, SMEM_DYN>>>(
        nullptr, nullptr, nullptr, 0, 0, 0, HD, 1, 1);
    k_softmax<<<(NH * L_TOT) / 8, thr>>>();
    k_gemm16<<<dim3(HD / BN, SEQ / BM, NH * NSEQ), thr, SMEM_DYN>>>(
        nullptr, nullptr, nullptr, 0, 0, 0, SEQ, 2, 2);

    // 5) output projection
    k_gemm16<<<dim3(HID / BN, L_TOT / BM), thr, SMEM_DYN>>>(p_attn16, p_WoT16, out, QD, QD, HID, QD, 0, 0);
}